// round 8
// baseline (speedup 1.0000x reference)
#include <cuda_runtime.h>
#include <cstdint>

typedef unsigned long long ULL;
typedef uint32_t U32;

#define C_DIMM 256
#define L_DIMM 2048
#define K_CB   8192
#define M_DIM  16384
#define EMB_N  4194304

#define BM 32            // rows per CTA
#define NSPLIT 8         // codebook splits
#define TILES_PER_SPLIT 8   // 8 tiles of 128 cols = 1024 cols per split

__device__ float g_csq[K_CB];
__device__ float g_l1x[M_DIM];
__device__ U32   g_xmax_bits;      // zero-init; atomicMax idempotent across replays
__device__ U32   g_cmax_bits;
__device__ U32   g_l1cmax_bits;
__device__ float g_scales[8];      // 0:s1 1:sc 2:twoS 3:inv_s1 4:inv_sc 5:margin_base
__device__ U32   g_qcb[K_CB * 64]; // codebook int8 packed (64 u32 per codeword)
__device__ ULL   g_part[M_DIM * NSPLIT * 4];
__device__ int   g_flag[M_DIM];
__device__ int   g_ncand[M_DIM];
__device__ int   g_cand[M_DIM * 8];
__device__ int   g_code[M_DIM];
__device__ float g_partial[EMB_N / 256];

// ---------------- helpers ----------------
__device__ __forceinline__ ULL makeKey(float s, int gk) {
    unsigned u = __float_as_uint(s);
    u = (u & 0x80000000u) ? ~u : (u | 0x80000000u);
    return ((ULL)u << 32) | (unsigned)(0xFFFFFFFFu - (unsigned)gk);
}
__device__ __forceinline__ float keyVal(ULL k) {
    unsigned v = (unsigned)(k >> 32);
    v = (v & 0x80000000u) ? (v ^ 0x80000000u) : ~v;
    return __uint_as_float(v);
}
__device__ __forceinline__ int keyIdx(ULL k) {
    return (int)(0xFFFFFFFFu - (unsigned)(k & 0xffffffffu));
}
__device__ __forceinline__ ULL maxk(ULL a, ULL b) { return a > b ? a : b; }

__device__ __forceinline__ void ins4(ULL* t, ULL k) {
    if (k > t[3]) {
        t[3] = k; ULL z;
        if (t[3] > t[2]) { z = t[2]; t[2] = t[3]; t[3] = z;
        if (t[2] > t[1]) { z = t[1]; t[1] = t[2]; t[2] = z;
        if (t[1] > t[0]) { z = t[0]; t[0] = t[1]; t[1] = z; } } }
    }
}
__device__ __forceinline__ U32 pack_s8(int q0, int q1, int q2, int q3) {
    return (q0 & 0xFF) | ((q1 & 0xFF) << 8) | ((q2 & 0xFF) << 16) | ((q3 & 0xFF) << 24);
}

// ---------------- kernel A: codebook stats (csq + global amax + L1max) -------
__global__ void cstat_kernel(const float* __restrict__ cb) {
    int k = blockIdx.x * 8 + (threadIdx.x >> 5);
    int lane = threadIdx.x & 31;
    const float* row = cb + (size_t)k * C_DIMM;
    float s = 0.0f, l1 = 0.0f, am = 0.0f;
    #pragma unroll
    for (int c = lane; c < C_DIMM; c += 32) {
        float v = row[c];
        s = fmaf(v, v, s);
        float a = fabsf(v);
        l1 += a;
        am = fmaxf(am, a);
    }
    #pragma unroll
    for (int o = 16; o > 0; o >>= 1) {
        s  += __shfl_xor_sync(0xffffffffu, s, o);
        l1 += __shfl_xor_sync(0xffffffffu, l1, o);
        am = fmaxf(am, __shfl_xor_sync(0xffffffffu, am, o));
    }
    if (lane == 0) {
        g_csq[k] = s;
        atomicMax(&g_cmax_bits, __float_as_uint(am));
        atomicMax(&g_l1cmax_bits, __float_as_uint(l1));
    }
}

// ---------------- kernel B: x stats (per-row L1 + global amax) ---------------
__global__ void xstat_kernel(const float* __restrict__ x) {
    int w = threadIdx.x >> 5, lane = threadIdx.x & 31;
    int row = blockIdx.x * 8 + w;
    int b = row >> 11, l = row & 2047;
    const float* xr = x + (size_t)b * C_DIMM * L_DIMM + l;
    float l1 = 0.0f, am = 0.0f;
    #pragma unroll
    for (int i = 0; i < 8; ++i) {
        float a = fabsf(xr[(size_t)(lane + 32 * i) * L_DIMM]);
        l1 += a;
        am = fmaxf(am, a);
    }
    #pragma unroll
    for (int o = 16; o > 0; o >>= 1) {
        l1 += __shfl_xor_sync(0xffffffffu, l1, o);
        am = fmaxf(am, __shfl_xor_sync(0xffffffffu, am, o));
    }
    if (lane == 0) {
        g_l1x[row] = l1;
        atomicMax(&g_xmax_bits, __float_as_uint(am));
    }
}

// ---------------- kernel C: derive scales ------------------------------------
__global__ void scale_kernel() {
    if (threadIdx.x == 0) {
        float xmax = __uint_as_float(g_xmax_bits);
        float cmax = __uint_as_float(g_cmax_bits);
        float l1cm = __uint_as_float(g_l1cmax_bits);
        float s1 = xmax * (1.0f / 32256.0f);
        float sc = cmax * (1.0f / 127.0f);
        g_scales[0] = s1;
        g_scales[1] = sc;
        g_scales[2] = 2.0f * s1 * sc;
        g_scales[3] = 32256.0f / xmax;
        g_scales[4] = 127.0f / cmax;
        g_scales[5] = s1 * l1cm + 128.0f * s1 * sc + 0.25f;  // margin base
    }
}

// ---------------- kernel D: quantize codebook to int8 ------------------------
__global__ void qcb_kernel(const float* __restrict__ cb) {
    int idx = blockIdx.x * 256 + threadIdx.x;   // < K_CB*64
    float inv_sc = g_scales[4];
    float4 v = *(const float4*)(cb + (size_t)idx * 4);
    int q0 = __float2int_rn(v.x * inv_sc);
    int q1 = __float2int_rn(v.y * inv_sc);
    int q2 = __float2int_rn(v.z * inv_sc);
    int q3 = __float2int_rn(v.w * inv_sc);
    g_qcb[idx] = pack_s8(q0, q1, q2, q3);
}

// ---------------- kernel E: dp4a GEMM + top-4 per (row, split) ---------------
__global__ __launch_bounds__(256, 2) void argmax_q(const float* __restrict__ x) {
    __shared__ U32 As_h[64 * 32];       // [k4][m] hi plane
    __shared__ U32 As_l[64 * 32];       // [k4][m] lo plane
    __shared__ U32 Bs[2][8 * 128];      // [buf][k4l*128 + col]

    const int tid = threadIdx.x;
    const int tx = tid & 15;
    const int ty = tid >> 4;

    const int rowTile = blockIdx.x >> 3;
    const int ksplit  = blockIdx.x & 7;
    const int rowBase = rowTile * BM;
    const int bidx = rowBase >> 11, l0 = rowBase & 2047;
    const float* xb = x + (size_t)bidx * (C_DIMM * L_DIMM) + l0;

    const float inv_s1 = g_scales[3];
    const float twoS   = g_scales[2];

    // ---- stage A: quantize 32 rows x 256 c into int8 hi/lo planes ----
    {
        const int mA = tid & 31;
        const int k4b = tid >> 5;       // 0..7
        #pragma unroll
        for (int it = 0; it < 8; ++it) {
            int k4g = it * 8 + k4b;
            int c0 = 4 * k4g;
            int qh[4], ql[4];
            #pragma unroll
            for (int j = 0; j < 4; ++j) {
                float v = xb[(size_t)(c0 + j) * L_DIMM + mA];
                int q = __float2int_rn(v * inv_s1);
                qh[j] = (q + 128) >> 8;
                ql[j] = q - (qh[j] << 8);
            }
            As_h[k4g * 32 + mA] = pack_s8(qh[0], qh[1], qh[2], qh[3]);
            As_l[k4g * 32 + mA] = pack_s8(ql[0], ql[1], ql[2], ql[3]);
        }
    }

    // B loader mapping
    const int ldcol = tid >> 1;
    const int ldh   = tid & 1;

    // preload chunk 0 (tile 0 of this split) into buf 0
    const int cwBase = ksplit * 1024;
    {
        uint4 v = *(const uint4*)&g_qcb[(size_t)(cwBase + ldcol) * 64 + ldh * 4];
        Bs[0][(ldh * 4 + 0) * 128 + ldcol] = v.x;
        Bs[0][(ldh * 4 + 1) * 128 + ldcol] = v.y;
        Bs[0][(ldh * 4 + 2) * 128 + ldcol] = v.z;
        Bs[0][(ldh * 4 + 3) * 128 + ldcol] = v.w;
    }
    __syncthreads();

    int acc_h[2][8], acc_l[2][8];
    #pragma unroll
    for (int r = 0; r < 2; ++r)
        #pragma unroll
        for (int j = 0; j < 8; ++j) { acc_h[r][j] = 0; acc_l[r][j] = 0; }

    ULL run[2][4];
    #pragma unroll
    for (int r = 0; r < 2; ++r)
        #pragma unroll
        for (int j = 0; j < 4; ++j) run[r][j] = 0ULL;

    for (int gc = 0; gc < TILES_PER_SPLIT * 8; ++gc) {   // 8 tiles x 8 chunks
        const int kt = gc >> 3, ch = gc & 7, buf = gc & 1;
        const bool more = (gc + 1 < TILES_PER_SPLIT * 8);

        uint4 nb;
        if (more) {
            const int nkt = (gc + 1) >> 3, nch = (gc + 1) & 7;
            nb = *(const uint4*)&g_qcb[(size_t)(cwBase + nkt * 128 + ldcol) * 64
                                       + nch * 8 + ldh * 4];
        }

        // ---- compute chunk (32 c) from Bs[buf] ----
        #pragma unroll
        for (int k4l = 0; k4l < 8; ++k4l) {
            const int k4g = ch * 8 + k4l;
            ULL ahp = *(const ULL*)&As_h[k4g * 32 + 2 * ty];
            ULL alp = *(const ULL*)&As_l[k4g * 32 + 2 * ty];
            U32 ah0 = (U32)ahp, ah1 = (U32)(ahp >> 32);
            U32 al0 = (U32)alp, al1 = (U32)(alp >> 32);
            uint4 b0 = *(const uint4*)&Bs[buf][k4l * 128 + 4 * tx];
            uint4 b1 = *(const uint4*)&Bs[buf][k4l * 128 + 64 + 4 * tx];
            const U32 bb[8] = {b0.x, b0.y, b0.z, b0.w, b1.x, b1.y, b1.z, b1.w};
            #pragma unroll
            for (int j = 0; j < 8; ++j) {
                acc_h[0][j] = __dp4a((int)ah0, (int)bb[j], acc_h[0][j]);
                acc_l[0][j] = __dp4a((int)al0, (int)bb[j], acc_l[0][j]);
                acc_h[1][j] = __dp4a((int)ah1, (int)bb[j], acc_h[1][j]);
                acc_l[1][j] = __dp4a((int)al1, (int)bb[j], acc_l[1][j]);
            }
        }

        // ---- store staged chunk to other buffer ----
        if (more) {
            Bs[buf ^ 1][(ldh * 4 + 0) * 128 + ldcol] = nb.x;
            Bs[buf ^ 1][(ldh * 4 + 1) * 128 + ldcol] = nb.y;
            Bs[buf ^ 1][(ldh * 4 + 2) * 128 + ldcol] = nb.z;
            Bs[buf ^ 1][(ldh * 4 + 3) * 128 + ldcol] = nb.w;
        }
        __syncthreads();

        // ---- tile finished: fold scores into per-lane top-4 ----
        if (ch == 7) {
            const int kbase = cwBase + kt * 128;
            #pragma unroll
            for (int g2 = 0; g2 < 2; ++g2) {
                float4 cq = __ldg((const float4*)&g_csq[kbase + g2 * 64 + 4 * tx]);
                const float cqa[4] = {cq.x, cq.y, cq.z, cq.w};
                #pragma unroll
                for (int j = 0; j < 4; ++j) {
                    int col = kbase + g2 * 64 + 4 * tx + j;
                    #pragma unroll
                    for (int r = 0; r < 2; ++r) {
                        int tot = acc_h[r][g2 * 4 + j] * 256 + acc_l[r][g2 * 4 + j];
                        float score = fmaf(-twoS, (float)tot, cqa[j]);
                        ins4(run[r], makeKey(score, col));
                        acc_h[r][g2 * 4 + j] = 0;
                        acc_l[r][g2 * 4 + j] = 0;
                    }
                }
            }
        }
    }

    // merge top-4 across the 16 tx lanes (xor < 16 keeps ty fixed)
    #pragma unroll
    for (int off = 1; off <= 8; off <<= 1) {
        #pragma unroll
        for (int r = 0; r < 2; ++r) {
            ULL t0 = __shfl_xor_sync(0xffffffffu, run[r][0], off);
            ULL t1 = __shfl_xor_sync(0xffffffffu, run[r][1], off);
            ULL t2 = __shfl_xor_sync(0xffffffffu, run[r][2], off);
            ULL t3 = __shfl_xor_sync(0xffffffffu, run[r][3], off);
            ins4(run[r], t0); ins4(run[r], t1); ins4(run[r], t2); ins4(run[r], t3);
        }
    }
    if (tx == 0) {
        #pragma unroll
        for (int r = 0; r < 2; ++r) {
            int row = rowBase + 2 * ty + r;
            ULL* dst = &g_part[((size_t)row * NSPLIT + ksplit) * 4];
            #pragma unroll
            for (int j = 0; j < 4; ++j) dst[j] = run[r][j];
        }
    }
}

// ---------------- kernel F: combine splits, margin test, emit candidates -----
__global__ void combine_kernel() {
    int row = blockIdx.x * 256 + threadIdx.x;
    if (row >= M_DIM) return;
    ULL top[4] = {0ULL, 0ULL, 0ULL, 0ULL};
    const ULL* p = &g_part[(size_t)row * NSPLIT * 4];
    #pragma unroll
    for (int i = 0; i < NSPLIT * 4; ++i) ins4(top, p[i]);

    float sc = g_scales[1];
    float marg = fmaf(sc, g_l1x[row], g_scales[5]);

    float v0 = keyVal(top[0]);
    int c0 = keyIdx(top[0]);
    g_code[row] = c0;

    if (v0 - keyVal(top[3]) <= marg) {
        g_flag[row] = 2;                       // can't bound candidate set: full rescan
    } else if (v0 - keyVal(top[1]) > marg) {
        g_flag[row] = 0;                       // provably exact
    } else {
        int nc = 1;
        g_cand[row * 8] = c0;
        #pragma unroll
        for (int j = 1; j < 3; ++j) {
            if (v0 - keyVal(top[j]) <= marg) { g_cand[row * 8 + nc] = keyIdx(top[j]); ++nc; }
        }
        g_flag[row] = 1;
        g_ncand[row] = nc;
    }
}

// ---------------- kernel G: exact-fp32 rescue for flagged rows ----------------
__global__ void rescue_kernel(const float* __restrict__ x, const float* __restrict__ cb) {
    __shared__ float xs[8][C_DIMM];
    int w = threadIdx.x >> 5, lane = threadIdx.x & 31;
    int row = blockIdx.x * 8 + w;
    int fl = g_flag[row];
    if (fl == 0) return;
    int b = row >> 11, l = row & 2047;
    const float* xr = x + (size_t)b * C_DIMM * L_DIMM + l;
    #pragma unroll
    for (int i = 0; i < 8; ++i) xs[w][lane + 32 * i] = xr[(size_t)(lane + 32 * i) * L_DIMM];
    __syncwarp();
    const float4* x4 = (const float4*)xs[w];
    ULL best = 0ULL;
    if (fl == 1) {
        int nc = g_ncand[row];
        if (lane < nc) {
            int k = g_cand[row * 8 + lane];
            const float4* cr = (const float4*)(cb + (size_t)k * C_DIMM);
            float d = 0.0f;
            #pragma unroll 8
            for (int i = 0; i < 64; ++i) {
                float4 a = x4[i], c = cr[i];
                d = fmaf(a.x, c.x, d); d = fmaf(a.y, c.y, d);
                d = fmaf(a.z, c.z, d); d = fmaf(a.w, c.w, d);
            }
            best = makeKey(fmaf(-2.0f, d, g_csq[k]), k);
        }
    } else {
        for (int k = lane; k < K_CB; k += 32) {
            const float4* cr = (const float4*)(cb + (size_t)k * C_DIMM);
            float d = 0.0f;
            #pragma unroll 8
            for (int i = 0; i < 64; ++i) {
                float4 a = x4[i], c = cr[i];
                d = fmaf(a.x, c.x, d); d = fmaf(a.y, c.y, d);
                d = fmaf(a.z, c.z, d); d = fmaf(a.w, c.w, d);
            }
            best = maxk(best, makeKey(fmaf(-2.0f, d, g_csq[k]), k));
        }
    }
    #pragma unroll
    for (int o = 16; o > 0; o >>= 1)
        best = maxk(best, __shfl_xor_sync(0xffffffffu, best, o));
    if (lane == 0 && best != 0ULL) g_code[row] = keyIdx(best);
}

// ---------------- output kernels ----------------
__global__ void code_cast_kernel(float* __restrict__ out_code) {
    int i = blockIdx.x * 256 + threadIdx.x;
    if (i < M_DIM) out_code[i] = (float)g_code[i];
}

__global__ void gather_loss_kernel(const float* __restrict__ x,
                                   const float* __restrict__ cb,
                                   float* __restrict__ emb_out) {
    __shared__ float sred[256];
    int idx = blockIdx.x * 256 + threadIdx.x;
    int bb = idx >> 19;
    int rem = idx & ((1 << 19) - 1);
    int c = rem >> 11;
    int l = rem & (L_DIMM - 1);
    int code = g_code[bb * L_DIMM + l];
    float v = __ldg(&cb[(size_t)code * C_DIMM + c]);
    emb_out[idx] = v;
    float d = x[idx] - v;
    sred[threadIdx.x] = d * d;
    __syncthreads();
    #pragma unroll
    for (int o = 128; o > 0; o >>= 1) {
        if (threadIdx.x < o) sred[threadIdx.x] += sred[threadIdx.x + o];
        __syncthreads();
    }
    if (threadIdx.x == 0) g_partial[blockIdx.x] = sred[0];
}

__global__ void finalize_kernel(float* __restrict__ loss_out) {
    __shared__ float sred[256];
    float s = 0.0f;
    for (int i = threadIdx.x; i < EMB_N / 256; i += 256) s += g_partial[i];
    sred[threadIdx.x] = s;
    __syncthreads();
    #pragma unroll
    for (int o = 128; o > 0; o >>= 1) {
        if (threadIdx.x < o) sred[threadIdx.x] += sred[threadIdx.x + o];
        __syncthreads();
    }
    if (threadIdx.x == 0) loss_out[0] = sred[0] * (1.0f / (float)EMB_N);
}

// ---------------- launch ----------------
extern "C" void kernel_launch(void* const* d_in, const int* in_sizes, int n_in,
                              void* d_out, int out_size) {
    const float* x  = (const float*)d_in[0];   // (8, 256, 2048)
    const float* cb = (const float*)d_in[1];   // (8192, 256)
    float* out = (float*)d_out;

    cstat_kernel<<<K_CB / 8, 256>>>(cb);
    xstat_kernel<<<M_DIM / 8, 256>>>(x);
    scale_kernel<<<1, 32>>>();
    qcb_kernel<<<K_CB * 64 / 256, 256>>>(cb);
    argmax_q<<<(M_DIM / BM) * NSPLIT, 256>>>(x);
    combine_kernel<<<M_DIM / 256, 256>>>();
    rescue_kernel<<<M_DIM / 8, 256>>>(x, cb);

    const int full = M_DIM + EMB_N + 1;
    if (out_size >= full) {
        code_cast_kernel<<<(M_DIM + 255) / 256, 256>>>(out);
        gather_loss_kernel<<<EMB_N / 256, 256>>>(x, cb, out + M_DIM);
        finalize_kernel<<<1, 256>>>(out + M_DIM + EMB_N);
    } else if (out_size == EMB_N) {
        gather_loss_kernel<<<EMB_N / 256, 256>>>(x, cb, out);
    } else if (out_size == M_DIM) {
        code_cast_kernel<<<(M_DIM + 255) / 256, 256>>>(out);
    } else {
        gather_loss_kernel<<<EMB_N / 256, 256>>>(x, cb, out);
    }
}

// round 9
// speedup vs baseline: 3.5099x; 3.5099x over previous
#include <cuda_runtime.h>

typedef unsigned long long ULL;

// Problem dims (static for this problem instance)
#define B_DIM 8
#define C_DIM 256
#define L_DIM 2048
#define K_CB  8192
#define M_DIM (B_DIM * L_DIM)           // 16384 rows (b,l)
#define EMB_N (B_DIM * C_DIM * L_DIM)   // 4194304 emb elements

// GEMM-argmax tiling
#define BM 64
#define BN 128
#define BK 32
#define NSPLIT 8                         // codebook splits (1024 words each)
#define KT_PER_SPLIT ((K_CB / BN) / NSPLIT)   // 8 tiles of 128

#define AS_STRIDE 132                    // 128 duplicated floats + 4 pad
#define AS_BUF (BK * AS_STRIDE)          // floats per A buffer
#define BS_BUF (BK * BN)                 // floats per B buffer
#define SMEM_FLOATS (2 * AS_BUF + 2 * BS_BUF)
#define SMEM_BYTES (SMEM_FLOATS * 4)

// Scratch (no allocation allowed in kernel_launch)
__device__ float g_csq[K_CB];
__device__ int   g_code[M_DIM];
__device__ ULL   g_part[M_DIM * NSPLIT];
__device__ float g_partial[EMB_N / 256];

// ---------------- packed f32x2 helpers -------------
__device__ __forceinline__ ULL fma2(ULL a, ULL b, ULL c) {
    ULL d;
    asm("fma.rn.f32x2 %0, %1, %2, %3;" : "=l"(d) : "l"(a), "l"(b), "l"(c));
    return d;
}

// monotone order-preserving key: larger score -> larger key; ties -> lower idx wins
__device__ __forceinline__ ULL makeKey(float s, int gk) {
    unsigned u = __float_as_uint(s);
    u = (u & 0x80000000u) ? ~u : (u | 0x80000000u);
    return ((ULL)u << 32) | (unsigned)(0xFFFFFFFFu - (unsigned)gk);
}
__device__ __forceinline__ ULL maxk(ULL a, ULL b) { return a > b ? a : b; }

// ---------------- kernel 1: codebook squared norms ---------------------------
__global__ void csq_kernel(const float* __restrict__ cb) {
    int k = blockIdx.x * 8 + (threadIdx.x >> 5);
    int lane = threadIdx.x & 31;
    const float* row = cb + (size_t)k * C_DIM;
    float s = 0.0f;
    #pragma unroll
    for (int c = lane; c < C_DIM; c += 32) { float v = row[c]; s = fmaf(v, v, s); }
    #pragma unroll
    for (int o = 16; o > 0; o >>= 1) s += __shfl_xor_sync(0xffffffffu, s, o);
    if (lane == 0) g_csq[k] = s;
}

// ---------------- kernel 2: fused GEMM + row argmax (split-K over codebook) --
// score(row, k) = ||c_k||^2 - 2 * dot(x_row, c_k)   (maximize; ties -> lowest k)
__global__ __launch_bounds__(256, 2) void argmax_kernel(const float* __restrict__ x,
                                                        const float* __restrict__ cb) {
    extern __shared__ float smem[];
    float* As = smem;                    // [2][BK][AS_STRIDE], A duplicated {a,a}
    float* Bs = smem + 2 * AS_BUF;       // [2][BK][BN]

    const int tid = threadIdx.x;
    const int tx = tid & 15;             // owns column pairs {2tx+32j, 2tx+1+32j}
    const int ty = tid >> 4;             // owns rows ty*4 .. ty*4+3

    const int rowTile = blockIdx.x >> 3;
    const int ksplit  = blockIdx.x & 7;
    const int rowBase = rowTile * BM;
    const int b  = rowBase / L_DIM;
    const int l0 = rowBase % L_DIM;
    const float* xb  = x  + (size_t)b * C_DIM * L_DIM + l0;
    const float* cbb = cb + (size_t)ksplit * (K_CB / NSPLIT) * C_DIM;

    // loader mappings
    const int a_c  = tid >> 3;           // 0..31 (c within chunk)
    const int a_m4 = tid & 7;            // float4 index base along m
    const int b_n  = tid & 127;          // codeword within tile
    const int b_cg = tid >> 7;           // 0/1, c-group base

    ULL run[4] = {0ULL, 0ULL, 0ULL, 0ULL};   // running best keys (leader lanes)

    for (int kt = 0; kt < KT_PER_SPLIT; ++kt) {
        const float* cbt = cbb + (size_t)kt * BN * C_DIM;
        const int kBase = ksplit * (K_CB / NSPLIT) + kt * BN;

        ULL acc[4][4];
        #pragma unroll
        for (int i = 0; i < 4; ++i)
            #pragma unroll
            for (int j = 0; j < 4; ++j) acc[i][j] = 0ULL;

        // hoisted epilogue csq loads: issue now, consume after the whole tile
        float2 cs[4];
        #pragma unroll
        for (int j = 0; j < 4; ++j)
            cs[j] = __ldg((const float2*)&g_csq[kBase + 2 * tx + 32 * j]);

        // ---- preload chunk 0 into buffer 0 ----
        {
            #pragma unroll
            for (int it = 0; it < 2; ++it) {
                int m4 = a_m4 + it * 8;
                float4 v = *(const float4*)(xb + (size_t)a_c * L_DIM + m4 * 4);
                float4 w0 = make_float4(v.x, v.x, v.y, v.y);
                float4 w1 = make_float4(v.z, v.z, v.w, v.w);
                *(float4*)&As[a_c * AS_STRIDE + m4 * 8]     = w0;
                *(float4*)&As[a_c * AS_STRIDE + m4 * 8 + 4] = w1;
            }
            const float* brow = cbt + (size_t)b_n * C_DIM;
            #pragma unroll
            for (int it = 0; it < 4; ++it) {
                int cg = b_cg + it * 2;
                float4 v = *(const float4*)(brow + cg * 4);
                Bs[(cg * 4 + 0) * BN + b_n] = v.x;
                Bs[(cg * 4 + 1) * BN + b_n] = v.y;
                Bs[(cg * 4 + 2) * BN + b_n] = v.z;
                Bs[(cg * 4 + 3) * BN + b_n] = v.w;
            }
        }
        __syncthreads();

        int buf = 0;
        for (int s = 0; s < C_DIM / BK; ++s) {
            // ---- issue gmem loads for chunk s+1 (into registers) ----
            float4 av[2], bv[4];
            const bool more = (s < C_DIM / BK - 1);
            if (more) {
                int ck = (s + 1) * BK;
                #pragma unroll
                for (int it = 0; it < 2; ++it) {
                    int m4 = a_m4 + it * 8;
                    av[it] = *(const float4*)(xb + (size_t)(ck + a_c) * L_DIM + m4 * 4);
                }
                const float* brow = cbt + (size_t)b_n * C_DIM + ck;
                #pragma unroll
                for (int it = 0; it < 4; ++it) {
                    int cg = b_cg + it * 2;
                    bv[it] = *(const float4*)(brow + cg * 4);
                }
            }

            // ---- compute on buffer buf ----
            const float* Ab = As + buf * AS_BUF + 8 * ty;
            const float* Bb = Bs + buf * BS_BUF + 2 * tx;
            #pragma unroll
            for (int k = 0; k < BK; ++k) {
                const ULL* ap = (const ULL*)(Ab + k * AS_STRIDE);
                ULL a0 = ap[0], a1 = ap[1], a2 = ap[2], a3 = ap[3];
                const float* br = Bb + k * BN;
                ULL b0 = *(const ULL*)(br);
                ULL b1 = *(const ULL*)(br + 32);
                ULL b2 = *(const ULL*)(br + 64);
                ULL b3 = *(const ULL*)(br + 96);
                acc[0][0] = fma2(a0, b0, acc[0][0]);
                acc[0][1] = fma2(a0, b1, acc[0][1]);
                acc[0][2] = fma2(a0, b2, acc[0][2]);
                acc[0][3] = fma2(a0, b3, acc[0][3]);
                acc[1][0] = fma2(a1, b0, acc[1][0]);
                acc[1][1] = fma2(a1, b1, acc[1][1]);
                acc[1][2] = fma2(a1, b2, acc[1][2]);
                acc[1][3] = fma2(a1, b3, acc[1][3]);
                acc[2][0] = fma2(a2, b0, acc[2][0]);
                acc[2][1] = fma2(a2, b1, acc[2][1]);
                acc[2][2] = fma2(a2, b2, acc[2][2]);
                acc[2][3] = fma2(a2, b3, acc[2][3]);
                acc[3][0] = fma2(a3, b0, acc[3][0]);
                acc[3][1] = fma2(a3, b1, acc[3][1]);
                acc[3][2] = fma2(a3, b2, acc[3][2]);
                acc[3][3] = fma2(a3, b3, acc[3][3]);
            }

            // ---- store staged chunk into the other buffer ----
            if (more) {
                float* Ad = As + (buf ^ 1) * AS_BUF;
                float* Bd = Bs + (buf ^ 1) * BS_BUF;
                #pragma unroll
                for (int it = 0; it < 2; ++it) {
                    int m4 = a_m4 + it * 8;
                    float4 v = av[it];
                    float4 w0 = make_float4(v.x, v.x, v.y, v.y);
                    float4 w1 = make_float4(v.z, v.z, v.w, v.w);
                    *(float4*)&Ad[a_c * AS_STRIDE + m4 * 8]     = w0;
                    *(float4*)&Ad[a_c * AS_STRIDE + m4 * 8 + 4] = w1;
                }
                #pragma unroll
                for (int it = 0; it < 4; ++it) {
                    int cg = b_cg + it * 2;
                    float4 v = bv[it];
                    Bd[(cg * 4 + 0) * BN + b_n] = v.x;
                    Bd[(cg * 4 + 1) * BN + b_n] = v.y;
                    Bd[(cg * 4 + 2) * BN + b_n] = v.z;
                    Bd[(cg * 4 + 3) * BN + b_n] = v.w;
                }
            }
            __syncthreads();
            buf ^= 1;
        }

        // ---- fold this codebook tile into running argmax (cs preloaded) ----
        #pragma unroll
        for (int i = 0; i < 4; ++i) {
            ULL best = 0ULL;
            #pragma unroll
            for (int j = 0; j < 4; ++j) {
                ULL a = acc[i][j];
                float dlo = __uint_as_float((unsigned)(a & 0xffffffffu));
                float dhi = __uint_as_float((unsigned)(a >> 32));
                int n0 = kBase + 2 * tx + 32 * j;
                float s0 = fmaf(-2.0f, dlo, cs[j].x);
                float s1 = fmaf(-2.0f, dhi, cs[j].y);
                best = maxk(best, makeKey(s0, n0));
                best = maxk(best, makeKey(s1, n0 + 1));
            }
            #pragma unroll
            for (int o = 8; o > 0; o >>= 1)
                best = maxk(best, __shfl_xor_sync(0xffffffffu, best, o));
            run[i] = maxk(run[i], best);
        }
    }

    if (tx == 0) {
        #pragma unroll
        for (int i = 0; i < 4; ++i) {
            int row = rowBase + ty * 4 + i;
            g_part[(size_t)row * NSPLIT + ksplit] = run[i];
        }
    }
}

// ---------------- kernel 3: combine split winners -> code + float out --------
__global__ void combine_cast_kernel(float* __restrict__ out_code) {
    int i = blockIdx.x * 256 + threadIdx.x;
    if (i >= M_DIM) return;
    const ULL* p = &g_part[(size_t)i * NSPLIT];
    ULL best = p[0];
    #pragma unroll
    for (int s = 1; s < NSPLIT; ++s) best = maxk(best, p[s]);
    int code = (int)(0xFFFFFFFFu - (unsigned)(best & 0xffffffffu));
    g_code[i] = code;
    if (out_code) out_code[i] = (float)code;
}

// ---------------- kernel 4: gather emb (B,C,L) + per-block loss partials -----
__global__ void gather_loss_kernel(const float* __restrict__ x,
                                   const float* __restrict__ cb,
                                   float* __restrict__ emb_out) {
    __shared__ float sred[256];
    int idx = blockIdx.x * 256 + threadIdx.x;     // < EMB_N
    int bb  = idx >> 19;                           // / (C*L)
    int rem = idx & ((1 << 19) - 1);
    int c   = rem >> 11;                           // / L
    int l   = rem & (L_DIM - 1);
    int code = g_code[bb * L_DIM + l];
    float v = __ldg(&cb[(size_t)code * C_DIM + c]);
    emb_out[idx] = v;
    float d = x[idx] - v;
    sred[threadIdx.x] = d * d;
    __syncthreads();
    #pragma unroll
    for (int o = 128; o > 0; o >>= 1) {
        if (threadIdx.x < o) sred[threadIdx.x] += sred[threadIdx.x + o];
        __syncthreads();
    }
    if (threadIdx.x == 0) g_partial[blockIdx.x] = sred[0];
}

// ---------------- kernel 5: deterministic final loss reduction ---------------
__global__ void finalize_kernel(float* __restrict__ loss_out) {
    __shared__ float sred[256];
    float s = 0.0f;
    for (int i = threadIdx.x; i < EMB_N / 256; i += 256) s += g_partial[i];
    sred[threadIdx.x] = s;
    __syncthreads();
    #pragma unroll
    for (int o = 128; o > 0; o >>= 1) {
        if (threadIdx.x < o) sred[threadIdx.x] += sred[threadIdx.x + o];
        __syncthreads();
    }
    if (threadIdx.x == 0) loss_out[0] = sred[0] * (1.0f / (float)EMB_N);
}

// ---------------- launch ------------------------------------------------------
extern "C" void kernel_launch(void* const* d_in, const int* in_sizes, int n_in,
                              void* d_out, int out_size) {
    const float* x  = (const float*)d_in[0];   // (8, 256, 2048)
    const float* cb = (const float*)d_in[1];   // (8192, 256)
    float* out = (float*)d_out;

    cudaFuncSetAttribute(argmax_kernel,
                         cudaFuncAttributeMaxDynamicSharedMemorySize, SMEM_BYTES);

    csq_kernel<<<K_CB / 8, 256>>>(cb);
    argmax_kernel<<<(M_DIM / BM) * NSPLIT, 256, SMEM_BYTES>>>(x, cb);

    const int full = M_DIM + EMB_N + 1;
    if (out_size >= full) {
        // layout: [code (16384), emb (4194304), loss (1)] in return order
        combine_cast_kernel<<<(M_DIM + 255) / 256, 256>>>(out);
        gather_loss_kernel<<<EMB_N / 256, 256>>>(x, cb, out + M_DIM);
        finalize_kernel<<<1, 256>>>(out + M_DIM + EMB_N);
    } else if (out_size == EMB_N) {
        combine_cast_kernel<<<(M_DIM + 255) / 256, 256>>>(nullptr);
        gather_loss_kernel<<<EMB_N / 256, 256>>>(x, cb, out);
    } else if (out_size == M_DIM) {
        combine_cast_kernel<<<(M_DIM + 255) / 256, 256>>>(out);
    } else {
        combine_cast_kernel<<<(M_DIM + 255) / 256, 256>>>(nullptr);
        gather_loss_kernel<<<EMB_N / 256, 256>>>(x, cb, out);
    }
}

// round 10
// speedup vs baseline: 4.1616x; 1.1857x over previous
#include <cuda_runtime.h>

typedef unsigned long long ULL;

// Problem dims (static for this problem instance)
#define B_DIM 8
#define C_DIM 256
#define L_DIM 2048
#define K_CB  8192
#define M_DIM (B_DIM * L_DIM)           // 16384 rows (b,l)
#define EMB_N (B_DIM * C_DIM * L_DIM)   // 4194304 emb elements

// GEMM-argmax tiling
#define BM 64
#define BN 128
#define BK 32
#define NSPLIT 8                         // codebook splits (1024 words each)
#define KT_PER_SPLIT ((K_CB / BN) / NSPLIT)   // 8 tiles of 128
#define NGC (KT_PER_SPLIT * (C_DIM / BK))     // 64 flattened chunk iterations

#define AST 68                           // A row stride (64 + 4 pad), float4-aligned
#define SM_A_FLOATS (C_DIM * AST)        // 17408 floats (resident A, all 256 k)
#define BS_BUF (BK * BN)                 // 4096 floats per B buffer
#define SMEM_FLOATS (SM_A_FLOATS + 2 * BS_BUF)
#define SMEM_BYTES (SMEM_FLOATS * 4)     // 102400 B -> occupancy 2

// Scratch (no allocation allowed in kernel_launch)
__device__ float g_csq[K_CB];
__device__ int   g_code[M_DIM];
__device__ ULL   g_part[M_DIM * NSPLIT];
__device__ float g_partial[EMB_N / 256];

// ---------------- packed f32x2 helpers -------------
__device__ __forceinline__ ULL fma2(ULL a, ULL b, ULL c) {
    ULL d;
    asm("fma.rn.f32x2 %0, %1, %2, %3;" : "=l"(d) : "l"(a), "l"(b), "l"(c));
    return d;
}
__device__ __forceinline__ ULL dup2(float v) {
    ULL d;
    unsigned u = __float_as_uint(v);
    asm("mov.b64 %0, {%1, %1};" : "=l"(d) : "r"(u));
    return d;
}

// monotone order-preserving key: larger score -> larger key; ties -> lower idx wins
__device__ __forceinline__ ULL makeKey(float s, int gk) {
    unsigned u = __float_as_uint(s);
    u = (u & 0x80000000u) ? ~u : (u | 0x80000000u);
    return ((ULL)u << 32) | (unsigned)(0xFFFFFFFFu - (unsigned)gk);
}
__device__ __forceinline__ ULL maxk(ULL a, ULL b) { return a > b ? a : b; }

// ---------------- kernel 1: codebook squared norms ---------------------------
__global__ void csq_kernel(const float* __restrict__ cb) {
    int k = blockIdx.x * 8 + (threadIdx.x >> 5);
    int lane = threadIdx.x & 31;
    const float* row = cb + (size_t)k * C_DIM;
    float s = 0.0f;
    #pragma unroll
    for (int c = lane; c < C_DIM; c += 32) { float v = row[c]; s = fmaf(v, v, s); }
    #pragma unroll
    for (int o = 16; o > 0; o >>= 1) s += __shfl_xor_sync(0xffffffffu, s, o);
    if (lane == 0) g_csq[k] = s;
}

// ---------------- kernel 2: fused GEMM + row argmax (split-K over codebook) --
// score(row, k) = ||c_k||^2 - 2 * dot(x_row, c_k)   (maximize; ties -> lowest k)
// A (64 rows x 256 c) resident in smem for the whole block; B double-buffered.
__global__ __launch_bounds__(256, 2) void argmax_kernel(const float* __restrict__ x,
                                                        const float* __restrict__ cb) {
    extern __shared__ float smem[];
    float* As = smem;                    // [256 k][AST] resident
    float* Bs = smem + SM_A_FLOATS;      // [2][BK][BN]

    const int tid = threadIdx.x;
    const int tx = tid & 15;             // owns column pairs {2tx+32j, 2tx+1+32j}
    const int ty = tid >> 4;             // owns rows ty*4 .. ty*4+3

    const int rowTile = blockIdx.x >> 3;
    const int ksplit  = blockIdx.x & 7;
    const int rowBase = rowTile * BM;
    const int b  = rowBase / L_DIM;
    const int l0 = rowBase % L_DIM;
    const float* xb  = x  + (size_t)b * C_DIM * L_DIM + l0;
    const float* cbb = cb + (size_t)ksplit * (K_CB / NSPLIT) * C_DIM;

    // ---- stage A once: 64 rows x 256 c, layout As[c][m] ----
    {
        const int m4 = tid & 15;         // float4 index along m (16 x 4 = 64)
        const int c0 = tid >> 4;         // 16 c per pass
        #pragma unroll
        for (int p = 0; p < 16; ++p) {
            int c = p * 16 + c0;
            float4 v = *(const float4*)(xb + (size_t)c * L_DIM + m4 * 4);
            *(float4*)&As[c * AST + m4 * 4] = v;
        }
    }

    // B loader mapping (unchanged from champion)
    const int b_n  = tid & 127;          // codeword within tile
    const int b_cg = tid >> 7;           // 0/1, c-group base

    // ---- preload B chunk gc=0 into buffer 0 ----
    {
        const float* brow = cbb + (size_t)b_n * C_DIM;
        #pragma unroll
        for (int it = 0; it < 4; ++it) {
            int cg = b_cg + it * 2;
            float4 v = *(const float4*)(brow + cg * 4);
            Bs[(cg * 4 + 0) * BN + b_n] = v.x;
            Bs[(cg * 4 + 1) * BN + b_n] = v.y;
            Bs[(cg * 4 + 2) * BN + b_n] = v.z;
            Bs[(cg * 4 + 3) * BN + b_n] = v.w;
        }
    }
    __syncthreads();

    ULL run[4] = {0ULL, 0ULL, 0ULL, 0ULL};
    ULL acc[4][4];
    #pragma unroll
    for (int i = 0; i < 4; ++i)
        #pragma unroll
        for (int j = 0; j < 4; ++j) acc[i][j] = 0ULL;

    for (int gc = 0; gc < NGC; ++gc) {   // 8 tiles x 8 chunks, flattened
        const int kt = gc >> 3, ch = gc & 7, buf = gc & 1;
        const bool more = (gc + 1 < NGC);

        // ---- issue gmem loads for the next B chunk (crosses tile boundaries) ----
        float4 bv[4];
        if (more) {
            const int nkt = (gc + 1) >> 3, nch = (gc + 1) & 7;
            const float* brow = cbb + (size_t)(nkt * BN + b_n) * C_DIM + nch * BK;
            #pragma unroll
            for (int it = 0; it < 4; ++it) {
                int cg = b_cg + it * 2;
                bv[it] = *(const float4*)(brow + cg * 4);
            }
        }

        // ---- compute chunk ch of tile kt: A resident, B from Bs[buf] ----
        const float* Arow = As + (size_t)(ch * BK) * AST + ty * 4;
        const float* Bb   = Bs + buf * BS_BUF + 2 * tx;
        #pragma unroll
        for (int k = 0; k < BK; ++k) {
            float4 a4 = *(const float4*)(Arow + k * AST);
            ULL aa0 = dup2(a4.x);
            ULL aa1 = dup2(a4.y);
            ULL aa2 = dup2(a4.z);
            ULL aa3 = dup2(a4.w);
            const float* br = Bb + k * BN;
            ULL b0 = *(const ULL*)(br);
            ULL b1 = *(const ULL*)(br + 32);
            ULL b2 = *(const ULL*)(br + 64);
            ULL b3 = *(const ULL*)(br + 96);
            acc[0][0] = fma2(aa0, b0, acc[0][0]);
            acc[0][1] = fma2(aa0, b1, acc[0][1]);
            acc[0][2] = fma2(aa0, b2, acc[0][2]);
            acc[0][3] = fma2(aa0, b3, acc[0][3]);
            acc[1][0] = fma2(aa1, b0, acc[1][0]);
            acc[1][1] = fma2(aa1, b1, acc[1][1]);
            acc[1][2] = fma2(aa1, b2, acc[1][2]);
            acc[1][3] = fma2(aa1, b3, acc[1][3]);
            acc[2][0] = fma2(aa2, b0, acc[2][0]);
            acc[2][1] = fma2(aa2, b1, acc[2][1]);
            acc[2][2] = fma2(aa2, b2, acc[2][2]);
            acc[2][3] = fma2(aa2, b3, acc[2][3]);
            acc[3][0] = fma2(aa3, b0, acc[3][0]);
            acc[3][1] = fma2(aa3, b1, acc[3][1]);
            acc[3][2] = fma2(aa3, b2, acc[3][2]);
            acc[3][3] = fma2(aa3, b3, acc[3][3]);
        }

        // ---- store staged B chunk into the other buffer ----
        if (more) {
            float* Bd = Bs + (buf ^ 1) * BS_BUF;
            #pragma unroll
            for (int it = 0; it < 4; ++it) {
                int cg = b_cg + it * 2;
                float4 v = bv[it];
                Bd[(cg * 4 + 0) * BN + b_n] = v.x;
                Bd[(cg * 4 + 1) * BN + b_n] = v.y;
                Bd[(cg * 4 + 2) * BN + b_n] = v.z;
                Bd[(cg * 4 + 3) * BN + b_n] = v.w;
            }
        }
        __syncthreads();

        // ---- tile finished: fold scores into running argmax ----
        if (ch == 7) {
            const int kBase = ksplit * (K_CB / NSPLIT) + kt * BN;
            float2 cs[4];
            #pragma unroll
            for (int j = 0; j < 4; ++j)
                cs[j] = __ldg((const float2*)&g_csq[kBase + 2 * tx + 32 * j]);
            #pragma unroll
            for (int i = 0; i < 4; ++i) {
                ULL best = 0ULL;
                #pragma unroll
                for (int j = 0; j < 4; ++j) {
                    ULL a = acc[i][j];
                    float dlo = __uint_as_float((unsigned)(a & 0xffffffffu));
                    float dhi = __uint_as_float((unsigned)(a >> 32));
                    int n0 = kBase + 2 * tx + 32 * j;
                    float s0 = fmaf(-2.0f, dlo, cs[j].x);
                    float s1 = fmaf(-2.0f, dhi, cs[j].y);
                    best = maxk(best, makeKey(s0, n0));
                    best = maxk(best, makeKey(s1, n0 + 1));
                    acc[i][j] = 0ULL;
                }
                #pragma unroll
                for (int o = 8; o > 0; o >>= 1)
                    best = maxk(best, __shfl_xor_sync(0xffffffffu, best, o));
                run[i] = maxk(run[i], best);
            }
        }
    }

    if (tx == 0) {
        #pragma unroll
        for (int i = 0; i < 4; ++i) {
            int row = rowBase + ty * 4 + i;
            g_part[(size_t)row * NSPLIT + ksplit] = run[i];
        }
    }
}

// ---------------- kernel 3: combine split winners -> code + float out --------
__global__ void combine_cast_kernel(float* __restrict__ out_code) {
    int i = blockIdx.x * 256 + threadIdx.x;
    if (i >= M_DIM) return;
    const ULL* p = &g_part[(size_t)i * NSPLIT];
    ULL best = p[0];
    #pragma unroll
    for (int s = 1; s < NSPLIT; ++s) best = maxk(best, p[s]);
    int code = (int)(0xFFFFFFFFu - (unsigned)(best & 0xffffffffu));
    g_code[i] = code;
    if (out_code) out_code[i] = (float)code;
}

// ---------------- kernel 4: gather emb (B,C,L) + per-block loss partials -----
__global__ void gather_loss_kernel(const float* __restrict__ x,
                                   const float* __restrict__ cb,
                                   float* __restrict__ emb_out) {
    __shared__ float sred[256];
    int idx = blockIdx.x * 256 + threadIdx.x;     // < EMB_N
    int bb  = idx >> 19;                           // / (C*L)
    int rem = idx & ((1 << 19) - 1);
    int c   = rem >> 11;                           // / L
    int l   = rem & (L_DIM - 1);
    int code = g_code[bb * L_DIM + l];
    float v = __ldg(&cb[(size_t)code * C_DIM + c]);
    emb_out[idx] = v;
    float d = x[idx] - v;
    sred[threadIdx.x] = d * d;
    __syncthreads();
    #pragma unroll
    for (int o = 128; o > 0; o >>= 1) {
        if (threadIdx.x < o) sred[threadIdx.x] += sred[threadIdx.x + o];
        __syncthreads();
    }
    if (threadIdx.x == 0) g_partial[blockIdx.x] = sred[0];
}

// ---------------- kernel 5: deterministic final loss reduction ---------------
__global__ void finalize_kernel(float* __restrict__ loss_out) {
    __shared__ float sred[256];
    float s = 0.0f;
    for (int i = threadIdx.x; i < EMB_N / 256; i += 256) s += g_partial[i];
    sred[threadIdx.x] = s;
    __syncthreads();
    #pragma unroll
    for (int o = 128; o > 0; o >>= 1) {
        if (threadIdx.x < o) sred[threadIdx.x] += sred[threadIdx.x + o];
        __syncthreads();
    }
    if (threadIdx.x == 0) loss_out[0] = sred[0] * (1.0f / (float)EMB_N);
}

// ---------------- launch ------------------------------------------------------
extern "C" void kernel_launch(void* const* d_in, const int* in_sizes, int n_in,
                              void* d_out, int out_size) {
    const float* x  = (const float*)d_in[0];   // (8, 256, 2048)
    const float* cb = (const float*)d_in[1];   // (8192, 256)
    float* out = (float*)d_out;

    cudaFuncSetAttribute(argmax_kernel,
                         cudaFuncAttributeMaxDynamicSharedMemorySize, SMEM_BYTES);

    csq_kernel<<<K_CB / 8, 256>>>(cb);
    argmax_kernel<<<(M_DIM / BM) * NSPLIT, 256, SMEM_BYTES>>>(x, cb);

    const int full = M_DIM + EMB_N + 1;
    if (out_size >= full) {
        // layout: [code (16384), emb (4194304), loss (1)] in return order
        combine_cast_kernel<<<(M_DIM + 255) / 256, 256>>>(out);
        gather_loss_kernel<<<EMB_N / 256, 256>>>(x, cb, out + M_DIM);
        finalize_kernel<<<1, 256>>>(out + M_DIM + EMB_N);
    } else if (out_size == EMB_N) {
        combine_cast_kernel<<<(M_DIM + 255) / 256, 256>>>(nullptr);
        gather_loss_kernel<<<EMB_N / 256, 256>>>(x, cb, out);
    } else if (out_size == M_DIM) {
        combine_cast_kernel<<<(M_DIM + 255) / 256, 256>>>(out);
    } else {
        combine_cast_kernel<<<(M_DIM + 255) / 256, 256>>>(nullptr);
        gather_loss_kernel<<<EMB_N / 256, 256>>>(x, cb, out);
    }
}

// round 11
// speedup vs baseline: 4.1976x; 1.0086x over previous
#include <cuda_runtime.h>

typedef unsigned long long ULL;

// Problem dims (static for this problem instance)
#define B_DIM 8
#define C_DIM 256
#define L_DIM 2048
#define K_CB  8192
#define M_DIM (B_DIM * L_DIM)           // 16384 rows (b,l)
#define EMB_N (B_DIM * C_DIM * L_DIM)   // 4194304 emb elements

// GEMM-argmax tiling
#define BM 64
#define BN 128
#define BK 32
#define NSPLIT 8                         // codebook splits (1024 words each)
#define KT_PER_SPLIT ((K_CB / BN) / NSPLIT)   // 8 tiles of 128
#define NGC (KT_PER_SPLIT * (C_DIM / BK))     // 64 flattened chunk iterations

#define AST 68                           // A row stride (64 + 4 pad), float4-aligned
#define SM_A_FLOATS (C_DIM * AST)        // 17408 floats (resident A, all 256 k)
#define BS_BUF (BK * BN)                 // 4096 floats per B buffer
#define SMEM_FLOATS (SM_A_FLOATS + 2 * BS_BUF)
#define SMEM_BYTES (SMEM_FLOATS * 4)     // 102400 B -> occupancy 2

// Scratch (no allocation allowed in kernel_launch)
__device__ float g_csq[K_CB];
__device__ int   g_code[M_DIM];
__device__ ULL   g_part[M_DIM * NSPLIT];
__device__ float g_partial[EMB_N / 1024];

// monotone order-preserving key: larger score -> larger key; ties -> lowest idx wins
__device__ __forceinline__ ULL makeKey(float s, int gk) {
    unsigned u = __float_as_uint(s);
    u = (u & 0x80000000u) ? ~u : (u | 0x80000000u);
    return ((ULL)u << 32) | (unsigned)(0xFFFFFFFFu - (unsigned)gk);
}
__device__ __forceinline__ ULL maxk(ULL a, ULL b) { return a > b ? a : b; }

// ---------------- kernel 1: codebook squared norms ---------------------------
__global__ void csq_kernel(const float* __restrict__ cb) {
    int k = blockIdx.x * 8 + (threadIdx.x >> 5);
    int lane = threadIdx.x & 31;
    const float* row = cb + (size_t)k * C_DIM;
    float s = 0.0f;
    #pragma unroll
    for (int c = lane; c < C_DIM; c += 32) { float v = row[c]; s = fmaf(v, v, s); }
    #pragma unroll
    for (int o = 16; o > 0; o >>= 1) s += __shfl_xor_sync(0xffffffffu, s, o);
    if (lane == 0) g_csq[k] = s;
}

// ---------------- kernel 2: fused GEMM + row argmax (split-K over codebook) --
// score(row, k) = ||c_k||^2 - 2 * dot(x_row, c_k)   (maximize; ties -> lowest k)
// A (64 rows x 256 c) resident in smem; B double-buffered; scalar-FFMA 4x8 tile.
__global__ __launch_bounds__(256, 2) void argmax_kernel(const float* __restrict__ x,
                                                        const float* __restrict__ cb) {
    extern __shared__ float smem[];
    float* As = smem;                    // [256 k][AST] resident
    float* Bs = smem + SM_A_FLOATS;      // [2][BK][BN]

    const int tid = threadIdx.x;
    const int tx = tid & 15;             // owns columns {4tx+j, 64+4tx+j}, j=0..3
    const int ty = tid >> 4;             // owns rows ty*4 .. ty*4+3

    const int rowTile = blockIdx.x >> 3;
    const int ksplit  = blockIdx.x & 7;
    const int rowBase = rowTile * BM;
    const int b  = rowBase / L_DIM;
    const int l0 = rowBase % L_DIM;
    const float* xb  = x  + (size_t)b * C_DIM * L_DIM + l0;
    const float* cbb = cb + (size_t)ksplit * (K_CB / NSPLIT) * C_DIM;

    // ---- stage A once: 64 rows x 256 c, layout As[c][m] ----
    {
        const int m4 = tid & 15;         // float4 index along m (16 x 4 = 64)
        const int c0 = tid >> 4;         // 16 c per pass
        #pragma unroll
        for (int p = 0; p < 16; ++p) {
            int c = p * 16 + c0;
            float4 v = *(const float4*)(xb + (size_t)c * L_DIM + m4 * 4);
            *(float4*)&As[c * AST + m4 * 4] = v;
        }
    }

    // B loader mapping
    const int b_n  = tid & 127;          // codeword within tile
    const int b_cg = tid >> 7;           // 0/1, c-group base

    // ---- preload B chunk gc=0 into buffer 0 ----
    {
        const float* brow = cbb + (size_t)b_n * C_DIM;
        #pragma unroll
        for (int it = 0; it < 4; ++it) {
            int cg = b_cg + it * 2;
            float4 v = *(const float4*)(brow + cg * 4);
            Bs[(cg * 4 + 0) * BN + b_n] = v.x;
            Bs[(cg * 4 + 1) * BN + b_n] = v.y;
            Bs[(cg * 4 + 2) * BN + b_n] = v.z;
            Bs[(cg * 4 + 3) * BN + b_n] = v.w;
        }
    }
    __syncthreads();

    ULL run[4] = {0ULL, 0ULL, 0ULL, 0ULL};
    float acc[4][8];
    #pragma unroll
    for (int i = 0; i < 4; ++i)
        #pragma unroll
        for (int j = 0; j < 8; ++j) acc[i][j] = 0.0f;

    for (int gc = 0; gc < NGC; ++gc) {   // 8 tiles x 8 chunks, flattened
        const int kt = gc >> 3, ch = gc & 7, buf = gc & 1;
        const bool more = (gc + 1 < NGC);

        // ---- issue gmem loads for the next B chunk (crosses tile boundaries) ----
        float4 bv[4];
        if (more) {
            const int nkt = (gc + 1) >> 3, nch = (gc + 1) & 7;
            const float* brow = cbb + (size_t)(nkt * BN + b_n) * C_DIM + nch * BK;
            #pragma unroll
            for (int it = 0; it < 4; ++it) {
                int cg = b_cg + it * 2;
                bv[it] = *(const float4*)(brow + cg * 4);
            }
        }

        // ---- compute chunk ch of tile kt: A resident, B from Bs[buf] ----
        const float* Arow = As + (size_t)(ch * BK) * AST + ty * 4;
        const float* Bb   = Bs + buf * BS_BUF + 4 * tx;
        #pragma unroll
        for (int k = 0; k < BK; ++k) {
            float4 a4 = *(const float4*)(Arow + k * AST);       // 16-lane broadcast
            const float* br = Bb + k * BN;
            float4 b0 = *(const float4*)(br);                    // cols 4tx+0..3
            float4 b1 = *(const float4*)(br + 64);               // cols 64+4tx+0..3
            const float av[4] = {a4.x, a4.y, a4.z, a4.w};
            const float bw[8] = {b0.x, b0.y, b0.z, b0.w, b1.x, b1.y, b1.z, b1.w};
            #pragma unroll
            for (int i = 0; i < 4; ++i)
                #pragma unroll
                for (int j = 0; j < 8; ++j)
                    acc[i][j] = fmaf(av[i], bw[j], acc[i][j]);
        }

        // ---- store staged B chunk into the other buffer ----
        if (more) {
            float* Bd = Bs + (buf ^ 1) * BS_BUF;
            #pragma unroll
            for (int it = 0; it < 4; ++it) {
                int cg = b_cg + it * 2;
                float4 v = bv[it];
                Bd[(cg * 4 + 0) * BN + b_n] = v.x;
                Bd[(cg * 4 + 1) * BN + b_n] = v.y;
                Bd[(cg * 4 + 2) * BN + b_n] = v.z;
                Bd[(cg * 4 + 3) * BN + b_n] = v.w;
            }
        }
        __syncthreads();

        // ---- tile finished: fold scores into running argmax ----
        if (ch == 7) {
            const int kBase = ksplit * (K_CB / NSPLIT) + kt * BN;
            float4 cs0 = __ldg((const float4*)&g_csq[kBase + 4 * tx]);
            float4 cs1 = __ldg((const float4*)&g_csq[kBase + 64 + 4 * tx]);
            const float csa[8] = {cs0.x, cs0.y, cs0.z, cs0.w,
                                  cs1.x, cs1.y, cs1.z, cs1.w};
            #pragma unroll
            for (int i = 0; i < 4; ++i) {
                ULL best = 0ULL;
                #pragma unroll
                for (int j = 0; j < 8; ++j) {
                    int n0 = kBase + ((j < 4) ? (4 * tx + j) : (64 + 4 * tx + j - 4));
                    float s = fmaf(-2.0f, acc[i][j], csa[j]);
                    best = maxk(best, makeKey(s, n0));
                    acc[i][j] = 0.0f;
                }
                #pragma unroll
                for (int o = 8; o > 0; o >>= 1)
                    best = maxk(best, __shfl_xor_sync(0xffffffffu, best, o));
                run[i] = maxk(run[i], best);
            }
        }
    }

    if (tx == 0) {
        #pragma unroll
        for (int i = 0; i < 4; ++i) {
            int row = rowBase + ty * 4 + i;
            g_part[(size_t)row * NSPLIT + ksplit] = run[i];
        }
    }
}

// ---------------- kernel 3: combine split winners -> code + float out --------
__global__ void combine_cast_kernel(float* __restrict__ out_code) {
    int i = blockIdx.x * 256 + threadIdx.x;
    if (i >= M_DIM) return;
    const ULL* p = &g_part[(size_t)i * NSPLIT];
    ULL best = p[0];
    #pragma unroll
    for (int s = 1; s < NSPLIT; ++s) best = maxk(best, p[s]);
    int code = (int)(0xFFFFFFFFu - (unsigned)(best & 0xffffffffu));
    g_code[i] = code;
    if (out_code) out_code[i] = (float)code;
}

// ---------------- kernel 4: gather emb (B,C,L) + loss partials (float4) ------
__global__ void gather_loss_kernel(const float* __restrict__ x,
                                   const float* __restrict__ cb,
                                   float* __restrict__ emb_out) {
    __shared__ float sred[256];
    int t = blockIdx.x * 256 + threadIdx.x;       // handles 4 consecutive elems
    int idx = t * 4;                               // < EMB_N
    int bb  = idx >> 19;                           // / (C*L)
    int rem = idx & ((1 << 19) - 1);
    int c   = rem >> 11;                           // / L
    int l   = rem & (L_DIM - 1);                   // multiple of 4
    int4 codes = *(const int4*)&g_code[bb * L_DIM + l];
    float4 xv = *(const float4*)&x[idx];
    float4 ev;
    ev.x = __ldg(&cb[(size_t)codes.x * C_DIM + c]);
    ev.y = __ldg(&cb[(size_t)codes.y * C_DIM + c]);
    ev.z = __ldg(&cb[(size_t)codes.z * C_DIM + c]);
    ev.w = __ldg(&cb[(size_t)codes.w * C_DIM + c]);
    *(float4*)&emb_out[idx] = ev;
    float dx = xv.x - ev.x, dy = xv.y - ev.y, dz = xv.z - ev.z, dw = xv.w - ev.w;
    sred[threadIdx.x] = dx * dx + dy * dy + dz * dz + dw * dw;
    __syncthreads();
    #pragma unroll
    for (int o = 128; o > 0; o >>= 1) {
        if (threadIdx.x < o) sred[threadIdx.x] += sred[threadIdx.x + o];
        __syncthreads();
    }
    if (threadIdx.x == 0) g_partial[blockIdx.x] = sred[0];
}

// ---------------- kernel 5: deterministic final loss reduction ---------------
__global__ void finalize_kernel(float* __restrict__ loss_out) {
    __shared__ float sred[256];
    float s = 0.0f;
    for (int i = threadIdx.x; i < EMB_N / 1024; i += 256) s += g_partial[i];
    sred[threadIdx.x] = s;
    __syncthreads();
    #pragma unroll
    for (int o = 128; o > 0; o >>= 1) {
        if (threadIdx.x < o) sred[threadIdx.x] += sred[threadIdx.x + o];
        __syncthreads();
    }
    if (threadIdx.x == 0) loss_out[0] = sred[0] * (1.0f / (float)EMB_N);
}

// ---------------- launch ------------------------------------------------------
extern "C" void kernel_launch(void* const* d_in, const int* in_sizes, int n_in,
                              void* d_out, int out_size) {
    const float* x  = (const float*)d_in[0];   // (8, 256, 2048)
    const float* cb = (const float*)d_in[1];   // (8192, 256)
    float* out = (float*)d_out;

    cudaFuncSetAttribute(argmax_kernel,
                         cudaFuncAttributeMaxDynamicSharedMemorySize, SMEM_BYTES);

    csq_kernel<<<K_CB / 8, 256>>>(cb);
    argmax_kernel<<<(M_DIM / BM) * NSPLIT, 256, SMEM_BYTES>>>(x, cb);

    const int full = M_DIM + EMB_N + 1;
    if (out_size >= full) {
        // layout: [code (16384), emb (4194304), loss (1)] in return order
        combine_cast_kernel<<<(M_DIM + 255) / 256, 256>>>(out);
        gather_loss_kernel<<<EMB_N / 1024, 256>>>(x, cb, out + M_DIM);
        finalize_kernel<<<1, 256>>>(out + M_DIM + EMB_N);
    } else if (out_size == EMB_N) {
        combine_cast_kernel<<<(M_DIM + 255) / 256, 256>>>(nullptr);
        gather_loss_kernel<<<EMB_N / 1024, 256>>>(x, cb, out);
    } else if (out_size == M_DIM) {
        combine_cast_kernel<<<(M_DIM + 255) / 256, 256>>>(out);
    } else {
        combine_cast_kernel<<<(M_DIM + 255) / 256, 256>>>(nullptr);
        gather_loss_kernel<<<EMB_N / 1024, 256>>>(x, cb, out);
    }
}

// round 12
// speedup vs baseline: 4.1984x; 1.0002x over previous
#include <cuda_runtime.h>

typedef unsigned long long ULL;

// Problem dims (static for this problem instance)
#define B_DIM 8
#define C_DIM 256
#define L_DIM 2048
#define K_CB  8192
#define M_DIM (B_DIM * L_DIM)           // 16384 rows (b,l)
#define EMB_N (B_DIM * C_DIM * L_DIM)   // 4194304 emb elements

// GEMM-argmax tiling
#define BM 64
#define BN 128
#define BK 32
#define NSPLIT 8                         // codebook splits (1024 words each)
#define KT_PER_SPLIT ((K_CB / BN) / NSPLIT)   // 8 tiles of 128
#define NGC (KT_PER_SPLIT * (C_DIM / BK))     // 64 flattened chunk iterations

#define AST 68                           // A row stride (64 + 4 pad), float4-aligned
#define SM_A_FLOATS (C_DIM * AST)        // 17408 floats (resident A, all 256 k)
#define BS_BUF (BK * BN)                 // 4096 floats per B buffer
#define SMEM_FLOATS (SM_A_FLOATS + 2 * BS_BUF)
#define SMEM_BYTES (SMEM_FLOATS * 4)     // 102400 B -> occupancy 2

// Scratch (no allocation allowed in kernel_launch)
__device__ float g_csq[K_CB];
__device__ int   g_code[M_DIM];
__device__ ULL   g_part[M_DIM * NSPLIT];
__device__ float g_partial[EMB_N / 2048];

// monotone order-preserving key: larger score -> larger key; ties -> lowest idx wins
__device__ __forceinline__ ULL makeKey(float s, int gk) {
    unsigned u = __float_as_uint(s);
    u = (u & 0x80000000u) ? ~u : (u | 0x80000000u);
    return ((ULL)u << 32) | (unsigned)(0xFFFFFFFFu - (unsigned)gk);
}
__device__ __forceinline__ ULL maxk(ULL a, ULL b) { return a > b ? a : b; }

// ---------------- kernel 1: codebook squared norms ---------------------------
__global__ void csq_kernel(const float* __restrict__ cb) {
    int k = blockIdx.x * 8 + (threadIdx.x >> 5);
    int lane = threadIdx.x & 31;
    const float* row = cb + (size_t)k * C_DIM;
    float s = 0.0f;
    #pragma unroll
    for (int c = lane; c < C_DIM; c += 32) { float v = row[c]; s = fmaf(v, v, s); }
    #pragma unroll
    for (int o = 16; o > 0; o >>= 1) s += __shfl_xor_sync(0xffffffffu, s, o);
    if (lane == 0) g_csq[k] = s;
}

// ---------------- kernel 2: fused GEMM + row argmax (split-K over codebook) --
// score(row, k) = ||c_k||^2 - 2 * dot(x_row, c_k)   (maximize; ties -> lowest k)
// A (64 rows x 256 c) resident in smem; B double-buffered; scalar-FFMA 4x8 tile.
// UNCHANGED from round 11 champion (at ~97.5% of the fp32 structural roofline).
__global__ __launch_bounds__(256, 2) void argmax_kernel(const float* __restrict__ x,
                                                        const float* __restrict__ cb) {
    extern __shared__ float smem[];
    float* As = smem;                    // [256 k][AST] resident
    float* Bs = smem + SM_A_FLOATS;      // [2][BK][BN]

    const int tid = threadIdx.x;
    const int tx = tid & 15;             // owns columns {4tx+j, 64+4tx+j}, j=0..3
    const int ty = tid >> 4;             // owns rows ty*4 .. ty*4+3

    const int rowTile = blockIdx.x >> 3;
    const int ksplit  = blockIdx.x & 7;
    const int rowBase = rowTile * BM;
    const int b  = rowBase / L_DIM;
    const int l0 = rowBase % L_DIM;
    const float* xb  = x  + (size_t)b * C_DIM * L_DIM + l0;
    const float* cbb = cb + (size_t)ksplit * (K_CB / NSPLIT) * C_DIM;

    // ---- stage A once: 64 rows x 256 c, layout As[c][m] ----
    {
        const int m4 = tid & 15;         // float4 index along m (16 x 4 = 64)
        const int c0 = tid >> 4;         // 16 c per pass
        #pragma unroll
        for (int p = 0; p < 16; ++p) {
            int c = p * 16 + c0;
            float4 v = *(const float4*)(xb + (size_t)c * L_DIM + m4 * 4);
            *(float4*)&As[c * AST + m4 * 4] = v;
        }
    }

    // B loader mapping
    const int b_n  = tid & 127;          // codeword within tile
    const int b_cg = tid >> 7;           // 0/1, c-group base

    // ---- preload B chunk gc=0 into buffer 0 ----
    {
        const float* brow = cbb + (size_t)b_n * C_DIM;
        #pragma unroll
        for (int it = 0; it < 4; ++it) {
            int cg = b_cg + it * 2;
            float4 v = *(const float4*)(brow + cg * 4);
            Bs[(cg * 4 + 0) * BN + b_n] = v.x;
            Bs[(cg * 4 + 1) * BN + b_n] = v.y;
            Bs[(cg * 4 + 2) * BN + b_n] = v.z;
            Bs[(cg * 4 + 3) * BN + b_n] = v.w;
        }
    }
    __syncthreads();

    ULL run[4] = {0ULL, 0ULL, 0ULL, 0ULL};
    float acc[4][8];
    #pragma unroll
    for (int i = 0; i < 4; ++i)
        #pragma unroll
        for (int j = 0; j < 8; ++j) acc[i][j] = 0.0f;

    for (int gc = 0; gc < NGC; ++gc) {   // 8 tiles x 8 chunks, flattened
        const int kt = gc >> 3, ch = gc & 7, buf = gc & 1;
        const bool more = (gc + 1 < NGC);

        // ---- issue gmem loads for the next B chunk (crosses tile boundaries) ----
        float4 bv[4];
        if (more) {
            const int nkt = (gc + 1) >> 3, nch = (gc + 1) & 7;
            const float* brow = cbb + (size_t)(nkt * BN + b_n) * C_DIM + nch * BK;
            #pragma unroll
            for (int it = 0; it < 4; ++it) {
                int cg = b_cg + it * 2;
                bv[it] = *(const float4*)(brow + cg * 4);
            }
        }

        // ---- compute chunk ch of tile kt: A resident, B from Bs[buf] ----
        const float* Arow = As + (size_t)(ch * BK) * AST + ty * 4;
        const float* Bb   = Bs + buf * BS_BUF + 4 * tx;
        #pragma unroll
        for (int k = 0; k < BK; ++k) {
            float4 a4 = *(const float4*)(Arow + k * AST);       // 16-lane broadcast
            const float* br = Bb + k * BN;
            float4 b0 = *(const float4*)(br);                    // cols 4tx+0..3
            float4 b1 = *(const float4*)(br + 64);               // cols 64+4tx+0..3
            const float av[4] = {a4.x, a4.y, a4.z, a4.w};
            const float bw[8] = {b0.x, b0.y, b0.z, b0.w, b1.x, b1.y, b1.z, b1.w};
            #pragma unroll
            for (int i = 0; i < 4; ++i)
                #pragma unroll
                for (int j = 0; j < 8; ++j)
                    acc[i][j] = fmaf(av[i], bw[j], acc[i][j]);
        }

        // ---- store staged B chunk into the other buffer ----
        if (more) {
            float* Bd = Bs + (buf ^ 1) * BS_BUF;
            #pragma unroll
            for (int it = 0; it < 4; ++it) {
                int cg = b_cg + it * 2;
                float4 v = bv[it];
                Bd[(cg * 4 + 0) * BN + b_n] = v.x;
                Bd[(cg * 4 + 1) * BN + b_n] = v.y;
                Bd[(cg * 4 + 2) * BN + b_n] = v.z;
                Bd[(cg * 4 + 3) * BN + b_n] = v.w;
            }
        }
        __syncthreads();

        // ---- tile finished: fold scores into running argmax ----
        if (ch == 7) {
            const int kBase = ksplit * (K_CB / NSPLIT) + kt * BN;
            float4 cs0 = __ldg((const float4*)&g_csq[kBase + 4 * tx]);
            float4 cs1 = __ldg((const float4*)&g_csq[kBase + 64 + 4 * tx]);
            const float csa[8] = {cs0.x, cs0.y, cs0.z, cs0.w,
                                  cs1.x, cs1.y, cs1.z, cs1.w};
            #pragma unroll
            for (int i = 0; i < 4; ++i) {
                ULL best = 0ULL;
                #pragma unroll
                for (int j = 0; j < 8; ++j) {
                    int n0 = kBase + ((j < 4) ? (4 * tx + j) : (64 + 4 * tx + j - 4));
                    float s = fmaf(-2.0f, acc[i][j], csa[j]);
                    best = maxk(best, makeKey(s, n0));
                    acc[i][j] = 0.0f;
                }
                #pragma unroll
                for (int o = 8; o > 0; o >>= 1)
                    best = maxk(best, __shfl_xor_sync(0xffffffffu, best, o));
                run[i] = maxk(run[i], best);
            }
        }
    }

    if (tx == 0) {
        #pragma unroll
        for (int i = 0; i < 4; ++i) {
            int row = rowBase + ty * 4 + i;
            g_part[(size_t)row * NSPLIT + ksplit] = run[i];
        }
    }
}

// ---------------- kernel 3: combine split winners -> code + float out --------
__global__ void combine_cast_kernel(float* __restrict__ out_code) {
    int i = blockIdx.x * 256 + threadIdx.x;
    if (i >= M_DIM) return;
    const ULL* p = &g_part[(size_t)i * NSPLIT];
    ULL best = p[0];
    #pragma unroll
    for (int s = 1; s < NSPLIT; ++s) best = maxk(best, p[s]);
    int code = (int)(0xFFFFFFFFu - (unsigned)(best & 0xffffffffu));
    g_code[i] = code;
    if (out_code) out_code[i] = (float)code;
}

// ---------------- kernel 4: gather emb (B,C,L) + loss partials (8/thread) ----
__global__ void gather_loss_kernel(const float* __restrict__ x,
                                   const float* __restrict__ cb,
                                   float* __restrict__ emb_out) {
    __shared__ float sred[256];
    int t = blockIdx.x * 256 + threadIdx.x;       // handles 8 consecutive elems
    int idx = t * 8;                               // < EMB_N
    int bb  = idx >> 19;                           // / (C*L)
    int rem = idx & ((1 << 19) - 1);
    int c   = rem >> 11;                           // / L
    int l   = rem & (L_DIM - 1);                   // multiple of 8
    float se = 0.0f;
    #pragma unroll
    for (int h = 0; h < 2; ++h) {
        int4 codes = *(const int4*)&g_code[bb * L_DIM + l + 4 * h];
        float4 xv = *(const float4*)&x[idx + 4 * h];
        float4 ev;
        ev.x = __ldg(&cb[(size_t)codes.x * C_DIM + c]);
        ev.y = __ldg(&cb[(size_t)codes.y * C_DIM + c]);
        ev.z = __ldg(&cb[(size_t)codes.z * C_DIM + c]);
        ev.w = __ldg(&cb[(size_t)codes.w * C_DIM + c]);
        *(float4*)&emb_out[idx + 4 * h] = ev;
        float dx = xv.x - ev.x, dy = xv.y - ev.y;
        float dz = xv.z - ev.z, dw = xv.w - ev.w;
        se += dx * dx + dy * dy + dz * dz + dw * dw;
    }
    sred[threadIdx.x] = se;
    __syncthreads();
    #pragma unroll
    for (int o = 128; o > 0; o >>= 1) {
        if (threadIdx.x < o) sred[threadIdx.x] += sred[threadIdx.x + o];
        __syncthreads();
    }
    if (threadIdx.x == 0) g_partial[blockIdx.x] = sred[0];
}

// ---------------- kernel 5: deterministic final loss reduction ---------------
__global__ void finalize_kernel(float* __restrict__ loss_out) {
    __shared__ float sred[256];
    float s = 0.0f;
    for (int i = threadIdx.x; i < EMB_N / 2048; i += 256) s += g_partial[i];
    sred[threadIdx.x] = s;
    __syncthreads();
    #pragma unroll
    for (int o = 128; o > 0; o >>= 1) {
        if (threadIdx.x < o) sred[threadIdx.x] += sred[threadIdx.x + o];
        __syncthreads();
    }
    if (threadIdx.x == 0) loss_out[0] = sred[0] * (1.0f / (float)EMB_N);
}

// ---------------- launch ------------------------------------------------------
extern "C" void kernel_launch(void* const* d_in, const int* in_sizes, int n_in,
                              void* d_out, int out_size) {
    const float* x  = (const float*)d_in[0];   // (8, 256, 2048)
    const float* cb = (const float*)d_in[1];   // (8192, 256)
    float* out = (float*)d_out;

    cudaFuncSetAttribute(argmax_kernel,
                         cudaFuncAttributeMaxDynamicSharedMemorySize, SMEM_BYTES);

    csq_kernel<<<K_CB / 8, 256>>>(cb);
    argmax_kernel<<<(M_DIM / BM) * NSPLIT, 256, SMEM_BYTES>>>(x, cb);

    const int full = M_DIM + EMB_N + 1;
    if (out_size >= full) {
        // layout: [code (16384), emb (4194304), loss (1)] in return order
        combine_cast_kernel<<<(M_DIM + 255) / 256, 256>>>(out);
        gather_loss_kernel<<<EMB_N / 2048, 256>>>(x, cb, out + M_DIM);
        finalize_kernel<<<1, 256>>>(out + M_DIM + EMB_N);
    } else if (out_size == EMB_N) {
        combine_cast_kernel<<<(M_DIM + 255) / 256, 256>>>(nullptr);
        gather_loss_kernel<<<EMB_N / 2048, 256>>>(x, cb, out);
    } else if (out_size == M_DIM) {
        combine_cast_kernel<<<(M_DIM + 255) / 256, 256>>>(out);
    } else {
        combine_cast_kernel<<<(M_DIM + 255) / 256, 256>>>(nullptr);
        gather_loss_kernel<<<EMB_N / 2048, 256>>>(x, cb, out);
    }
}

// round 13
// speedup vs baseline: 4.2106x; 1.0029x over previous
#include <cuda_runtime.h>

typedef unsigned long long ULL;

// Problem dims (static for this problem instance)
#define B_DIM 8
#define C_DIM 256
#define L_DIM 2048
#define K_CB  8192
#define M_DIM (B_DIM * L_DIM)           // 16384 rows (b,l)
#define EMB_N (B_DIM * C_DIM * L_DIM)   // 4194304 emb elements

// GEMM-argmax tiling
#define BM 64
#define BN 128
#define BK 32
#define NSPLIT 8                         // codebook splits (1024 words each)
#define KT_PER_SPLIT ((K_CB / BN) / NSPLIT)   // 8 tiles of 128
#define NGC (KT_PER_SPLIT * (C_DIM / BK))     // 64 flattened chunk iterations

#define AST 68                           // A row stride (64 + 4 pad), float4-aligned
#define SM_A_FLOATS (C_DIM * AST)        // 17408 floats (resident A, all 256 k)
#define BS_BUF (BK * BN)                 // 4096 floats per B buffer
#define SMEM_FLOATS (SM_A_FLOATS + 2 * BS_BUF)
#define SMEM_BYTES (SMEM_FLOATS * 4)     // 102400 B -> occupancy 2

// gather kernel: 8 l's per block
#define GL_CHUNK 8
#define GL_BLOCKS (M_DIM / GL_CHUNK)     // 2048
#define GST 264                          // smem row stride (256 + 8 pad)

// Scratch (no allocation allowed in kernel_launch)
__device__ float g_csq[K_CB];
__device__ int   g_code[M_DIM];
__device__ ULL   g_part[M_DIM * NSPLIT];
__device__ float g_partial[GL_BLOCKS];

// monotone order-preserving key: larger score -> larger key; ties -> lowest idx wins
__device__ __forceinline__ ULL makeKey(float s, int gk) {
    unsigned u = __float_as_uint(s);
    u = (u & 0x80000000u) ? ~u : (u | 0x80000000u);
    return ((ULL)u << 32) | (unsigned)(0xFFFFFFFFu - (unsigned)gk);
}
__device__ __forceinline__ ULL maxk(ULL a, ULL b) { return a > b ? a : b; }

// ---------------- kernel 1: codebook squared norms ---------------------------
__global__ void csq_kernel(const float* __restrict__ cb) {
    int k = blockIdx.x * 8 + (threadIdx.x >> 5);
    int lane = threadIdx.x & 31;
    const float* row = cb + (size_t)k * C_DIM;
    float s = 0.0f;
    #pragma unroll
    for (int c = lane; c < C_DIM; c += 32) { float v = row[c]; s = fmaf(v, v, s); }
    #pragma unroll
    for (int o = 16; o > 0; o >>= 1) s += __shfl_xor_sync(0xffffffffu, s, o);
    if (lane == 0) g_csq[k] = s;
}

// ---------------- kernel 2: fused GEMM + row argmax (split-K over codebook) --
// score(row, k) = ||c_k||^2 - 2 * dot(x_row, c_k)   (maximize; ties -> lowest k)
// A (64 rows x 256 c) resident in smem; B double-buffered; scalar-FFMA 4x8 tile.
// UNCHANGED champion (at ~97.5% of the fp32 structural roofline).
__global__ __launch_bounds__(256, 2) void argmax_kernel(const float* __restrict__ x,
                                                        const float* __restrict__ cb) {
    extern __shared__ float smem[];
    float* As = smem;                    // [256 k][AST] resident
    float* Bs = smem + SM_A_FLOATS;      // [2][BK][BN]

    const int tid = threadIdx.x;
    const int tx = tid & 15;             // owns columns {4tx+j, 64+4tx+j}, j=0..3
    const int ty = tid >> 4;             // owns rows ty*4 .. ty*4+3

    const int rowTile = blockIdx.x >> 3;
    const int ksplit  = blockIdx.x & 7;
    const int rowBase = rowTile * BM;
    const int b  = rowBase / L_DIM;
    const int l0 = rowBase % L_DIM;
    const float* xb  = x  + (size_t)b * C_DIM * L_DIM + l0;
    const float* cbb = cb + (size_t)ksplit * (K_CB / NSPLIT) * C_DIM;

    // ---- stage A once: 64 rows x 256 c, layout As[c][m] ----
    {
        const int m4 = tid & 15;         // float4 index along m (16 x 4 = 64)
        const int c0 = tid >> 4;         // 16 c per pass
        #pragma unroll
        for (int p = 0; p < 16; ++p) {
            int c = p * 16 + c0;
            float4 v = *(const float4*)(xb + (size_t)c * L_DIM + m4 * 4);
            *(float4*)&As[c * AST + m4 * 4] = v;
        }
    }

    // B loader mapping
    const int b_n  = tid & 127;          // codeword within tile
    const int b_cg = tid >> 7;           // 0/1, c-group base

    // ---- preload B chunk gc=0 into buffer 0 ----
    {
        const float* brow = cbb + (size_t)b_n * C_DIM;
        #pragma unroll
        for (int it = 0; it < 4; ++it) {
            int cg = b_cg + it * 2;
            float4 v = *(const float4*)(brow + cg * 4);
            Bs[(cg * 4 + 0) * BN + b_n] = v.x;
            Bs[(cg * 4 + 1) * BN + b_n] = v.y;
            Bs[(cg * 4 + 2) * BN + b_n] = v.z;
            Bs[(cg * 4 + 3) * BN + b_n] = v.w;
        }
    }
    __syncthreads();

    ULL run[4] = {0ULL, 0ULL, 0ULL, 0ULL};
    float acc[4][8];
    #pragma unroll
    for (int i = 0; i < 4; ++i)
        #pragma unroll
        for (int j = 0; j < 8; ++j) acc[i][j] = 0.0f;

    for (int gc = 0; gc < NGC; ++gc) {   // 8 tiles x 8 chunks, flattened
        const int kt = gc >> 3, ch = gc & 7, buf = gc & 1;
        const bool more = (gc + 1 < NGC);

        // ---- issue gmem loads for the next B chunk (crosses tile boundaries) ----
        float4 bv[4];
        if (more) {
            const int nkt = (gc + 1) >> 3, nch = (gc + 1) & 7;
            const float* brow = cbb + (size_t)(nkt * BN + b_n) * C_DIM + nch * BK;
            #pragma unroll
            for (int it = 0; it < 4; ++it) {
                int cg = b_cg + it * 2;
                bv[it] = *(const float4*)(brow + cg * 4);
            }
        }

        // ---- compute chunk ch of tile kt: A resident, B from Bs[buf] ----
        const float* Arow = As + (size_t)(ch * BK) * AST + ty * 4;
        const float* Bb   = Bs + buf * BS_BUF + 4 * tx;
        #pragma unroll
        for (int k = 0; k < BK; ++k) {
            float4 a4 = *(const float4*)(Arow + k * AST);       // 16-lane broadcast
            const float* br = Bb + k * BN;
            float4 b0 = *(const float4*)(br);                    // cols 4tx+0..3
            float4 b1 = *(const float4*)(br + 64);               // cols 64+4tx+0..3
            const float av[4] = {a4.x, a4.y, a4.z, a4.w};
            const float bw[8] = {b0.x, b0.y, b0.z, b0.w, b1.x, b1.y, b1.z, b1.w};
            #pragma unroll
            for (int i = 0; i < 4; ++i)
                #pragma unroll
                for (int j = 0; j < 8; ++j)
                    acc[i][j] = fmaf(av[i], bw[j], acc[i][j]);
        }

        // ---- store staged B chunk into the other buffer ----
        if (more) {
            float* Bd = Bs + (buf ^ 1) * BS_BUF;
            #pragma unroll
            for (int it = 0; it < 4; ++it) {
                int cg = b_cg + it * 2;
                float4 v = bv[it];
                Bd[(cg * 4 + 0) * BN + b_n] = v.x;
                Bd[(cg * 4 + 1) * BN + b_n] = v.y;
                Bd[(cg * 4 + 2) * BN + b_n] = v.z;
                Bd[(cg * 4 + 3) * BN + b_n] = v.w;
            }
        }
        __syncthreads();

        // ---- tile finished: fold scores into running argmax ----
        if (ch == 7) {
            const int kBase = ksplit * (K_CB / NSPLIT) + kt * BN;
            float4 cs0 = __ldg((const float4*)&g_csq[kBase + 4 * tx]);
            float4 cs1 = __ldg((const float4*)&g_csq[kBase + 64 + 4 * tx]);
            const float csa[8] = {cs0.x, cs0.y, cs0.z, cs0.w,
                                  cs1.x, cs1.y, cs1.z, cs1.w};
            #pragma unroll
            for (int i = 0; i < 4; ++i) {
                ULL best = 0ULL;
                #pragma unroll
                for (int j = 0; j < 8; ++j) {
                    int n0 = kBase + ((j < 4) ? (4 * tx + j) : (64 + 4 * tx + j - 4));
                    float s = fmaf(-2.0f, acc[i][j], csa[j]);
                    best = maxk(best, makeKey(s, n0));
                    acc[i][j] = 0.0f;
                }
                #pragma unroll
                for (int o = 8; o > 0; o >>= 1)
                    best = maxk(best, __shfl_xor_sync(0xffffffffu, best, o));
                run[i] = maxk(run[i], best);
            }
        }
    }

    if (tx == 0) {
        #pragma unroll
        for (int i = 0; i < 4; ++i) {
            int row = rowBase + ty * 4 + i;
            g_part[(size_t)row * NSPLIT + ksplit] = run[i];
        }
    }
}

// ---------------- kernel 3: combine split winners -> code + float out --------
__global__ void combine_cast_kernel(float* __restrict__ out_code) {
    int i = blockIdx.x * 256 + threadIdx.x;
    if (i >= M_DIM) return;
    const ULL* p = &g_part[(size_t)i * NSPLIT];
    ULL best = p[0];
    #pragma unroll
    for (int s = 1; s < NSPLIT; ++s) best = maxk(best, p[s]);
    int code = (int)(0xFFFFFFFFu - (unsigned)(best & 0xffffffffu));
    g_code[i] = code;
    if (out_code) out_code[i] = (float)code;
}

// ---------------- kernel 4: gather emb + loss, smem-staged codebook rows -----
// One block per (b, 8-l chunk): stage the 8 selected codebook rows coalesced,
// then thread c writes emb[b][c][l0..l0+7] (2x float4) and folds the loss.
__global__ __launch_bounds__(256) void gather_loss_kernel(const float* __restrict__ x,
                                                          const float* __restrict__ cb,
                                                          float* __restrict__ emb_out) {
    __shared__ float rows[GL_CHUNK * GST];   // 8 codebook rows, padded
    __shared__ float sred[256];
    __shared__ int   codes[GL_CHUNK];

    const int tid = threadIdx.x;
    const int bb = blockIdx.x >> 8;           // / (L_DIM / GL_CHUNK) = / 256
    const int l0 = (blockIdx.x & 255) * GL_CHUNK;

    if (tid < GL_CHUNK) codes[tid] = g_code[bb * L_DIM + l0 + tid];
    __syncthreads();

    // stage 8 rows: each warp loads one row via float4 (2KB coalesced)
    {
        const int w = tid >> 5, lane = tid & 31;
        const float4* src = (const float4*)(cb + (size_t)codes[w] * C_DIM);
        float4* dst = (float4*)&rows[w * GST];
        dst[lane]      = src[lane];
        dst[lane + 32] = src[lane + 32];
    }
    __syncthreads();

    // thread c: read 8 staged values (padded stride -> conflict-spread),
    // write 8 contiguous emb elements, fold loss from 8 contiguous x reads.
    const int c = tid;
    const size_t base = (size_t)bb * (C_DIM * L_DIM) + (size_t)c * L_DIM + l0;
    float4 e0, e1;
    e0.x = rows[0 * GST + c]; e0.y = rows[1 * GST + c];
    e0.z = rows[2 * GST + c]; e0.w = rows[3 * GST + c];
    e1.x = rows[4 * GST + c]; e1.y = rows[5 * GST + c];
    e1.z = rows[6 * GST + c]; e1.w = rows[7 * GST + c];
    float4 x0 = *(const float4*)&x[base];
    float4 x1 = *(const float4*)&x[base + 4];
    *(float4*)&emb_out[base]     = e0;
    *(float4*)&emb_out[base + 4] = e1;
    float d0 = x0.x - e0.x, d1 = x0.y - e0.y, d2 = x0.z - e0.z, d3 = x0.w - e0.w;
    float d4 = x1.x - e1.x, d5 = x1.y - e1.y, d6 = x1.z - e1.z, d7 = x1.w - e1.w;
    sred[tid] = d0 * d0 + d1 * d1 + d2 * d2 + d3 * d3
              + d4 * d4 + d5 * d5 + d6 * d6 + d7 * d7;
    __syncthreads();
    #pragma unroll
    for (int o = 128; o > 0; o >>= 1) {
        if (tid < o) sred[tid] += sred[tid + o];
        __syncthreads();
    }
    if (tid == 0) g_partial[blockIdx.x] = sred[0];
}

// ---------------- kernel 5: deterministic final loss reduction ---------------
__global__ void finalize_kernel(float* __restrict__ loss_out) {
    __shared__ float sred[256];
    float s = 0.0f;
    for (int i = threadIdx.x; i < GL_BLOCKS; i += 256) s += g_partial[i];
    sred[threadIdx.x] = s;
    __syncthreads();
    #pragma unroll
    for (int o = 128; o > 0; o >>= 1) {
        if (threadIdx.x < o) sred[threadIdx.x] += sred[threadIdx.x + o];
        __syncthreads();
    }
    if (threadIdx.x == 0) loss_out[0] = sred[0] * (1.0f / (float)EMB_N);
}

// ---------------- launch ------------------------------------------------------
extern "C" void kernel_launch(void* const* d_in, const int* in_sizes, int n_in,
                              void* d_out, int out_size) {
    const float* x  = (const float*)d_in[0];   // (8, 256, 2048)
    const float* cb = (const float*)d_in[1];   // (8192, 256)
    float* out = (float*)d_out;

    cudaFuncSetAttribute(argmax_kernel,
                         cudaFuncAttributeMaxDynamicSharedMemorySize, SMEM_BYTES);

    csq_kernel<<<K_CB / 8, 256>>>(cb);
    argmax_kernel<<<(M_DIM / BM) * NSPLIT, 256, SMEM_BYTES>>>(x, cb);

    const int full = M_DIM + EMB_N + 1;
    if (out_size >= full) {
        // layout: [code (16384), emb (4194304), loss (1)] in return order
        combine_cast_kernel<<<(M_DIM + 255) / 256, 256>>>(out);
        gather_loss_kernel<<<GL_BLOCKS, 256>>>(x, cb, out + M_DIM);
        finalize_kernel<<<1, 256>>>(out + M_DIM + EMB_N);
    } else if (out_size == EMB_N) {
        combine_cast_kernel<<<(M_DIM + 255) / 256, 256>>>(nullptr);
        gather_loss_kernel<<<GL_BLOCKS, 256>>>(x, cb, out);
    } else if (out_size == M_DIM) {
        combine_cast_kernel<<<(M_DIM + 255) / 256, 256>>>(out);
    } else {
        combine_cast_kernel<<<(M_DIM + 255) / 256, 256>>>(nullptr);
        gather_loss_kernel<<<GL_BLOCKS, 256>>>(x, cb, out);
    }
}

// round 14
// speedup vs baseline: 4.2206x; 1.0024x over previous
#include <cuda_runtime.h>

typedef unsigned long long ULL;

// Problem dims (static for this problem instance)
#define B_DIM 8
#define C_DIM 256
#define L_DIM 2048
#define K_CB  8192
#define M_DIM (B_DIM * L_DIM)           // 16384 rows (b,l)
#define EMB_N (B_DIM * C_DIM * L_DIM)   // 4194304 emb elements

// GEMM-argmax tiling
#define BM 64
#define BN 128
#define BK 32
#define NSPLIT 8                         // codebook splits (1024 words each)
#define KT_PER_SPLIT ((K_CB / BN) / NSPLIT)   // 8 tiles of 128
#define NGC (KT_PER_SPLIT * (C_DIM / BK))     // 64 flattened chunk iterations

#define AST 68                           // A row stride (64 + 4 pad), float4-aligned
#define SM_A_FLOATS (C_DIM * AST)        // 17408 floats (resident A, all 256 k)
#define BS_BUF (BK * BN)                 // 4096 floats per B buffer
#define SMEM_FLOATS (SM_A_FLOATS + 2 * BS_BUF)
#define SMEM_BYTES (SMEM_FLOATS * 4)     // 102400 B -> occupancy 2

// gather kernel: 8 l's per block
#define GL_CHUNK 8
#define GL_BLOCKS (M_DIM / GL_CHUNK)     // 2048
#define GST 264                          // smem row stride (256 + 8 pad)

// Scratch (no allocation allowed in kernel_launch)
__device__ float g_csq[K_CB];
__device__ int   g_code[M_DIM];
__device__ ULL   g_part[M_DIM * NSPLIT];
__device__ float g_partial[GL_BLOCKS];

// monotone order-preserving key: larger score -> larger key; ties -> lowest idx wins
__device__ __forceinline__ ULL makeKey(float s, int gk) {
    unsigned u = __float_as_uint(s);
    u = (u & 0x80000000u) ? ~u : (u | 0x80000000u);
    return ((ULL)u << 32) | (unsigned)(0xFFFFFFFFu - (unsigned)gk);
}
__device__ __forceinline__ ULL maxk(ULL a, ULL b) { return a > b ? a : b; }
__device__ __forceinline__ int combineRow(int row) {
    const ULL* p = &g_part[(size_t)row * NSPLIT];
    ULL best = p[0];
    #pragma unroll
    for (int s = 1; s < NSPLIT; ++s) best = maxk(best, p[s]);
    return (int)(0xFFFFFFFFu - (unsigned)(best & 0xffffffffu));
}

// ---------------- kernel 1: codebook squared norms ---------------------------
__global__ void csq_kernel(const float* __restrict__ cb) {
    int k = blockIdx.x * 8 + (threadIdx.x >> 5);
    int lane = threadIdx.x & 31;
    const float* row = cb + (size_t)k * C_DIM;
    float s = 0.0f;
    #pragma unroll
    for (int c = lane; c < C_DIM; c += 32) { float v = row[c]; s = fmaf(v, v, s); }
    #pragma unroll
    for (int o = 16; o > 0; o >>= 1) s += __shfl_xor_sync(0xffffffffu, s, o);
    if (lane == 0) g_csq[k] = s;
}

// ---------------- kernel 2: fused GEMM + row argmax (split-K over codebook) --
// UNCHANGED champion (at ~97.5% of the fp32 structural roofline).
__global__ __launch_bounds__(256, 2) void argmax_kernel(const float* __restrict__ x,
                                                        const float* __restrict__ cb) {
    extern __shared__ float smem[];
    float* As = smem;                    // [256 k][AST] resident
    float* Bs = smem + SM_A_FLOATS;      // [2][BK][BN]

    const int tid = threadIdx.x;
    const int tx = tid & 15;             // owns columns {4tx+j, 64+4tx+j}, j=0..3
    const int ty = tid >> 4;             // owns rows ty*4 .. ty*4+3

    const int rowTile = blockIdx.x >> 3;
    const int ksplit  = blockIdx.x & 7;
    const int rowBase = rowTile * BM;
    const int b  = rowBase / L_DIM;
    const int l0 = rowBase % L_DIM;
    const float* xb  = x  + (size_t)b * C_DIM * L_DIM + l0;
    const float* cbb = cb + (size_t)ksplit * (K_CB / NSPLIT) * C_DIM;

    // ---- stage A once: 64 rows x 256 c, layout As[c][m] ----
    {
        const int m4 = tid & 15;
        const int c0 = tid >> 4;
        #pragma unroll
        for (int p = 0; p < 16; ++p) {
            int c = p * 16 + c0;
            float4 v = *(const float4*)(xb + (size_t)c * L_DIM + m4 * 4);
            *(float4*)&As[c * AST + m4 * 4] = v;
        }
    }

    // B loader mapping
    const int b_n  = tid & 127;
    const int b_cg = tid >> 7;

    // ---- preload B chunk gc=0 into buffer 0 ----
    {
        const float* brow = cbb + (size_t)b_n * C_DIM;
        #pragma unroll
        for (int it = 0; it < 4; ++it) {
            int cg = b_cg + it * 2;
            float4 v = *(const float4*)(brow + cg * 4);
            Bs[(cg * 4 + 0) * BN + b_n] = v.x;
            Bs[(cg * 4 + 1) * BN + b_n] = v.y;
            Bs[(cg * 4 + 2) * BN + b_n] = v.z;
            Bs[(cg * 4 + 3) * BN + b_n] = v.w;
        }
    }
    __syncthreads();

    ULL run[4] = {0ULL, 0ULL, 0ULL, 0ULL};
    float acc[4][8];
    #pragma unroll
    for (int i = 0; i < 4; ++i)
        #pragma unroll
        for (int j = 0; j < 8; ++j) acc[i][j] = 0.0f;

    for (int gc = 0; gc < NGC; ++gc) {   // 8 tiles x 8 chunks, flattened
        const int kt = gc >> 3, ch = gc & 7, buf = gc & 1;
        const bool more = (gc + 1 < NGC);

        float4 bv[4];
        if (more) {
            const int nkt = (gc + 1) >> 3, nch = (gc + 1) & 7;
            const float* brow = cbb + (size_t)(nkt * BN + b_n) * C_DIM + nch * BK;
            #pragma unroll
            for (int it = 0; it < 4; ++it) {
                int cg = b_cg + it * 2;
                bv[it] = *(const float4*)(brow + cg * 4);
            }
        }

        const float* Arow = As + (size_t)(ch * BK) * AST + ty * 4;
        const float* Bb   = Bs + buf * BS_BUF + 4 * tx;
        #pragma unroll
        for (int k = 0; k < BK; ++k) {
            float4 a4 = *(const float4*)(Arow + k * AST);
            const float* br = Bb + k * BN;
            float4 b0 = *(const float4*)(br);
            float4 b1 = *(const float4*)(br + 64);
            const float av[4] = {a4.x, a4.y, a4.z, a4.w};
            const float bw[8] = {b0.x, b0.y, b0.z, b0.w, b1.x, b1.y, b1.z, b1.w};
            #pragma unroll
            for (int i = 0; i < 4; ++i)
                #pragma unroll
                for (int j = 0; j < 8; ++j)
                    acc[i][j] = fmaf(av[i], bw[j], acc[i][j]);
        }

        if (more) {
            float* Bd = Bs + (buf ^ 1) * BS_BUF;
            #pragma unroll
            for (int it = 0; it < 4; ++it) {
                int cg = b_cg + it * 2;
                float4 v = bv[it];
                Bd[(cg * 4 + 0) * BN + b_n] = v.x;
                Bd[(cg * 4 + 1) * BN + b_n] = v.y;
                Bd[(cg * 4 + 2) * BN + b_n] = v.z;
                Bd[(cg * 4 + 3) * BN + b_n] = v.w;
            }
        }
        __syncthreads();

        if (ch == 7) {
            const int kBase = ksplit * (K_CB / NSPLIT) + kt * BN;
            float4 cs0 = __ldg((const float4*)&g_csq[kBase + 4 * tx]);
            float4 cs1 = __ldg((const float4*)&g_csq[kBase + 64 + 4 * tx]);
            const float csa[8] = {cs0.x, cs0.y, cs0.z, cs0.w,
                                  cs1.x, cs1.y, cs1.z, cs1.w};
            #pragma unroll
            for (int i = 0; i < 4; ++i) {
                ULL best = 0ULL;
                #pragma unroll
                for (int j = 0; j < 8; ++j) {
                    int n0 = kBase + ((j < 4) ? (4 * tx + j) : (64 + 4 * tx + j - 4));
                    float s = fmaf(-2.0f, acc[i][j], csa[j]);
                    best = maxk(best, makeKey(s, n0));
                    acc[i][j] = 0.0f;
                }
                #pragma unroll
                for (int o = 8; o > 0; o >>= 1)
                    best = maxk(best, __shfl_xor_sync(0xffffffffu, best, o));
                run[i] = maxk(run[i], best);
            }
        }
    }

    if (tx == 0) {
        #pragma unroll
        for (int i = 0; i < 4; ++i) {
            int row = rowBase + ty * 4 + i;
            g_part[(size_t)row * NSPLIT + ksplit] = run[i];
        }
    }
}

// ---------------- kernel 3: standalone combine (fallback branch only) --------
__global__ void combine_cast_kernel(float* __restrict__ out_code) {
    int i = blockIdx.x * 256 + threadIdx.x;
    if (i >= M_DIM) return;
    int code = combineRow(i);
    g_code[i] = code;
    if (out_code) out_code[i] = (float)code;
}

// ---------------- kernel 4: FUSED combine + gather emb + loss ----------------
// One block per (b, 8-l chunk). Threads 0-7 combine the 8-split winners for the
// block's 8 rows (each row belongs to exactly one block), emit out_code, then
// all 256 threads stage the 8 selected codebook rows and write emb + loss.
__global__ __launch_bounds__(256) void gather_loss_kernel(const float* __restrict__ x,
                                                          const float* __restrict__ cb,
                                                          float* __restrict__ emb_out,
                                                          float* __restrict__ out_code) {
    __shared__ float rows[GL_CHUNK * GST];   // 8 codebook rows, padded
    __shared__ float sred[256];
    __shared__ int   codes[GL_CHUNK];

    const int tid = threadIdx.x;
    const int bb = blockIdx.x >> 8;           // / (L_DIM / GL_CHUNK) = / 256
    const int l0 = (blockIdx.x & 255) * GL_CHUNK;

    if (tid < GL_CHUNK) {
        int row = bb * L_DIM + l0 + tid;
        int code = combineRow(row);
        codes[tid] = code;
        if (out_code) out_code[row] = (float)code;
    }
    __syncthreads();

    // stage 8 rows: each warp loads one row via float4 (2KB coalesced)
    {
        const int w = tid >> 5, lane = tid & 31;
        const float4* src = (const float4*)(cb + (size_t)codes[w] * C_DIM);
        float4* dst = (float4*)&rows[w * GST];
        dst[lane]      = src[lane];
        dst[lane + 32] = src[lane + 32];
    }
    __syncthreads();

    const int c = tid;
    const size_t base = (size_t)bb * (C_DIM * L_DIM) + (size_t)c * L_DIM + l0;
    float4 e0, e1;
    e0.x = rows[0 * GST + c]; e0.y = rows[1 * GST + c];
    e0.z = rows[2 * GST + c]; e0.w = rows[3 * GST + c];
    e1.x = rows[4 * GST + c]; e1.y = rows[5 * GST + c];
    e1.z = rows[6 * GST + c]; e1.w = rows[7 * GST + c];
    float4 x0 = *(const float4*)&x[base];
    float4 x1 = *(const float4*)&x[base + 4];
    *(float4*)&emb_out[base]     = e0;
    *(float4*)&emb_out[base + 4] = e1;
    float d0 = x0.x - e0.x, d1 = x0.y - e0.y, d2 = x0.z - e0.z, d3 = x0.w - e0.w;
    float d4 = x1.x - e1.x, d5 = x1.y - e1.y, d6 = x1.z - e1.z, d7 = x1.w - e1.w;
    sred[tid] = d0 * d0 + d1 * d1 + d2 * d2 + d3 * d3
              + d4 * d4 + d5 * d5 + d6 * d6 + d7 * d7;
    __syncthreads();
    #pragma unroll
    for (int o = 128; o > 0; o >>= 1) {
        if (tid < o) sred[tid] += sred[tid + o];
        __syncthreads();
    }
    if (tid == 0) g_partial[blockIdx.x] = sred[0];
}

// ---------------- kernel 5: deterministic final loss reduction ---------------
__global__ void finalize_kernel(float* __restrict__ loss_out) {
    __shared__ float sred[256];
    float s = 0.0f;
    for (int i = threadIdx.x; i < GL_BLOCKS; i += 256) s += g_partial[i];
    sred[threadIdx.x] = s;
    __syncthreads();
    #pragma unroll
    for (int o = 128; o > 0; o >>= 1) {
        if (threadIdx.x < o) sred[threadIdx.x] += sred[threadIdx.x + o];
        __syncthreads();
    }
    if (threadIdx.x == 0) loss_out[0] = sred[0] * (1.0f / (float)EMB_N);
}

// ---------------- launch ------------------------------------------------------
extern "C" void kernel_launch(void* const* d_in, const int* in_sizes, int n_in,
                              void* d_out, int out_size) {
    const float* x  = (const float*)d_in[0];   // (8, 256, 2048)
    const float* cb = (const float*)d_in[1];   // (8192, 256)
    float* out = (float*)d_out;

    cudaFuncSetAttribute(argmax_kernel,
                         cudaFuncAttributeMaxDynamicSharedMemorySize, SMEM_BYTES);

    csq_kernel<<<K_CB / 8, 256>>>(cb);
    argmax_kernel<<<(M_DIM / BM) * NSPLIT, 256, SMEM_BYTES>>>(x, cb);

    const int full = M_DIM + EMB_N + 1;
    if (out_size >= full) {
        // layout: [code (16384), emb (4194304), loss (1)] in return order
        gather_loss_kernel<<<GL_BLOCKS, 256>>>(x, cb, out + M_DIM, out);
        finalize_kernel<<<1, 256>>>(out + M_DIM + EMB_N);
    } else if (out_size == EMB_N) {
        gather_loss_kernel<<<GL_BLOCKS, 256>>>(x, cb, out, nullptr);
    } else if (out_size == M_DIM) {
        combine_cast_kernel<<<(M_DIM + 255) / 256, 256>>>(out);
    } else {
        gather_loss_kernel<<<GL_BLOCKS, 256>>>(x, cb, out, nullptr);
    }
}

// round 15
// speedup vs baseline: 4.2249x; 1.0010x over previous
#include <cuda_runtime.h>

typedef unsigned long long ULL;

// Problem dims (static for this problem instance)
#define B_DIM 8
#define C_DIM 256
#define L_DIM 2048
#define K_CB  8192
#define M_DIM (B_DIM * L_DIM)           // 16384 rows (b,l)
#define EMB_N (B_DIM * C_DIM * L_DIM)   // 4194304 emb elements

// GEMM-argmax tiling
#define BM 64
#define BN 128
#define BK 32
#define NSPLIT 8                         // codebook splits (1024 words each)
#define KT_PER_SPLIT ((K_CB / BN) / NSPLIT)   // 8 tiles of 128
#define NGC (KT_PER_SPLIT * (C_DIM / BK))     // 64 flattened chunk iterations

#define AST 68                           // A row stride (64 + 4 pad), float4-aligned
#define SM_A_FLOATS (C_DIM * AST)        // 17408 floats (resident A, all 256 k)
#define BS_BUF (BK * BN)                 // 4096 floats per B buffer
#define SMEM_FLOATS (SM_A_FLOATS + 2 * BS_BUF)
#define SMEM_BYTES (SMEM_FLOATS * 4)     // 102400 B -> occupancy 2

// gather kernel: 8 l's per block
#define GL_CHUNK 8
#define GL_BLOCKS (M_DIM / GL_CHUNK)     // 2048
#define GST 264                          // smem row stride (256 + 8 pad)

// Scratch (no allocation allowed in kernel_launch)
__device__ float g_csq[K_CB];
__device__ int   g_code[M_DIM];
__device__ ULL   g_part[M_DIM * NSPLIT];
__device__ float g_partial[GL_BLOCKS];

// monotone order-preserving key: larger score -> larger key; ties -> lowest idx wins
__device__ __forceinline__ ULL makeKey(float s, int gk) {
    unsigned u = __float_as_uint(s);
    u = (u & 0x80000000u) ? ~u : (u | 0x80000000u);
    return ((ULL)u << 32) | (unsigned)(0xFFFFFFFFu - (unsigned)gk);
}
__device__ __forceinline__ ULL maxk(ULL a, ULL b) { return a > b ? a : b; }
__device__ __forceinline__ int combineRow(int row) {
    const ULL* p = &g_part[(size_t)row * NSPLIT];
    ULL best = p[0];
    #pragma unroll
    for (int s = 1; s < NSPLIT; ++s) best = maxk(best, p[s]);
    return (int)(0xFFFFFFFFu - (unsigned)(best & 0xffffffffu));
}

// ---------------- kernel 1: codebook squared norms (float4) ------------------
__global__ void csq_kernel(const float* __restrict__ cb) {
    int k = blockIdx.x * 8 + (threadIdx.x >> 5);
    int lane = threadIdx.x & 31;
    const float4* row = (const float4*)(cb + (size_t)k * C_DIM);
    float s = 0.0f;
    #pragma unroll
    for (int c4 = lane; c4 < C_DIM / 4; c4 += 32) {
        float4 v = row[c4];
        s = fmaf(v.x, v.x, s);
        s = fmaf(v.y, v.y, s);
        s = fmaf(v.z, v.z, s);
        s = fmaf(v.w, v.w, s);
    }
    #pragma unroll
    for (int o = 16; o > 0; o >>= 1) s += __shfl_xor_sync(0xffffffffu, s, o);
    if (lane == 0) g_csq[k] = s;
}

// ---------------- kernel 2: fused GEMM + row argmax (split-K over codebook) --
// UNCHANGED champion (at ~97.5% of the fp32 structural roofline).
__global__ __launch_bounds__(256, 2) void argmax_kernel(const float* __restrict__ x,
                                                        const float* __restrict__ cb) {
    extern __shared__ float smem[];
    float* As = smem;                    // [256 k][AST] resident
    float* Bs = smem + SM_A_FLOATS;      // [2][BK][BN]

    const int tid = threadIdx.x;
    const int tx = tid & 15;             // owns columns {4tx+j, 64+4tx+j}, j=0..3
    const int ty = tid >> 4;             // owns rows ty*4 .. ty*4+3

    const int rowTile = blockIdx.x >> 3;
    const int ksplit  = blockIdx.x & 7;
    const int rowBase = rowTile * BM;
    const int b  = rowBase / L_DIM;
    const int l0 = rowBase % L_DIM;
    const float* xb  = x  + (size_t)b * C_DIM * L_DIM + l0;
    const float* cbb = cb + (size_t)ksplit * (K_CB / NSPLIT) * C_DIM;

    // ---- stage A once: 64 rows x 256 c, layout As[c][m] ----
    {
        const int m4 = tid & 15;
        const int c0 = tid >> 4;
        #pragma unroll
        for (int p = 0; p < 16; ++p) {
            int c = p * 16 + c0;
            float4 v = *(const float4*)(xb + (size_t)c * L_DIM + m4 * 4);
            *(float4*)&As[c * AST + m4 * 4] = v;
        }
    }

    // B loader mapping
    const int b_n  = tid & 127;
    const int b_cg = tid >> 7;

    // ---- preload B chunk gc=0 into buffer 0 ----
    {
        const float* brow = cbb + (size_t)b_n * C_DIM;
        #pragma unroll
        for (int it = 0; it < 4; ++it) {
            int cg = b_cg + it * 2;
            float4 v = *(const float4*)(brow + cg * 4);
            Bs[(cg * 4 + 0) * BN + b_n] = v.x;
            Bs[(cg * 4 + 1) * BN + b_n] = v.y;
            Bs[(cg * 4 + 2) * BN + b_n] = v.z;
            Bs[(cg * 4 + 3) * BN + b_n] = v.w;
        }
    }
    __syncthreads();

    ULL run[4] = {0ULL, 0ULL, 0ULL, 0ULL};
    float acc[4][8];
    #pragma unroll
    for (int i = 0; i < 4; ++i)
        #pragma unroll
        for (int j = 0; j < 8; ++j) acc[i][j] = 0.0f;

    for (int gc = 0; gc < NGC; ++gc) {   // 8 tiles x 8 chunks, flattened
        const int kt = gc >> 3, ch = gc & 7, buf = gc & 1;
        const bool more = (gc + 1 < NGC);

        float4 bv[4];
        if (more) {
            const int nkt = (gc + 1) >> 3, nch = (gc + 1) & 7;
            const float* brow = cbb + (size_t)(nkt * BN + b_n) * C_DIM + nch * BK;
            #pragma unroll
            for (int it = 0; it < 4; ++it) {
                int cg = b_cg + it * 2;
                bv[it] = *(const float4*)(brow + cg * 4);
            }
        }

        const float* Arow = As + (size_t)(ch * BK) * AST + ty * 4;
        const float* Bb   = Bs + buf * BS_BUF + 4 * tx;
        #pragma unroll
        for (int k = 0; k < BK; ++k) {
            float4 a4 = *(const float4*)(Arow + k * AST);
            const float* br = Bb + k * BN;
            float4 b0 = *(const float4*)(br);
            float4 b1 = *(const float4*)(br + 64);
            const float av[4] = {a4.x, a4.y, a4.z, a4.w};
            const float bw[8] = {b0.x, b0.y, b0.z, b0.w, b1.x, b1.y, b1.z, b1.w};
            #pragma unroll
            for (int i = 0; i < 4; ++i)
                #pragma unroll
                for (int j = 0; j < 8; ++j)
                    acc[i][j] = fmaf(av[i], bw[j], acc[i][j]);
        }

        if (more) {
            float* Bd = Bs + (buf ^ 1) * BS_BUF;
            #pragma unroll
            for (int it = 0; it < 4; ++it) {
                int cg = b_cg + it * 2;
                float4 v = bv[it];
                Bd[(cg * 4 + 0) * BN + b_n] = v.x;
                Bd[(cg * 4 + 1) * BN + b_n] = v.y;
                Bd[(cg * 4 + 2) * BN + b_n] = v.z;
                Bd[(cg * 4 + 3) * BN + b_n] = v.w;
            }
        }
        __syncthreads();

        if (ch == 7) {
            const int kBase = ksplit * (K_CB / NSPLIT) + kt * BN;
            float4 cs0 = __ldg((const float4*)&g_csq[kBase + 4 * tx]);
            float4 cs1 = __ldg((const float4*)&g_csq[kBase + 64 + 4 * tx]);
            const float csa[8] = {cs0.x, cs0.y, cs0.z, cs0.w,
                                  cs1.x, cs1.y, cs1.z, cs1.w};
            #pragma unroll
            for (int i = 0; i < 4; ++i) {
                ULL best = 0ULL;
                #pragma unroll
                for (int j = 0; j < 8; ++j) {
                    int n0 = kBase + ((j < 4) ? (4 * tx + j) : (64 + 4 * tx + j - 4));
                    float s = fmaf(-2.0f, acc[i][j], csa[j]);
                    best = maxk(best, makeKey(s, n0));
                    acc[i][j] = 0.0f;
                }
                #pragma unroll
                for (int o = 8; o > 0; o >>= 1)
                    best = maxk(best, __shfl_xor_sync(0xffffffffu, best, o));
                run[i] = maxk(run[i], best);
            }
        }
    }

    if (tx == 0) {
        #pragma unroll
        for (int i = 0; i < 4; ++i) {
            int row = rowBase + ty * 4 + i;
            g_part[(size_t)row * NSPLIT + ksplit] = run[i];
        }
    }
}

// ---------------- kernel 3: standalone combine (fallback branch only) --------
__global__ void combine_cast_kernel(float* __restrict__ out_code) {
    int i = blockIdx.x * 256 + threadIdx.x;
    if (i >= M_DIM) return;
    int code = combineRow(i);
    g_code[i] = code;
    if (out_code) out_code[i] = (float)code;
}

// ---------------- kernel 4: FUSED combine + gather emb + loss ----------------
__global__ __launch_bounds__(256) void gather_loss_kernel(const float* __restrict__ x,
                                                          const float* __restrict__ cb,
                                                          float* __restrict__ emb_out,
                                                          float* __restrict__ out_code) {
    __shared__ float rows[GL_CHUNK * GST];   // 8 codebook rows, padded
    __shared__ float sred[256];
    __shared__ int   codes[GL_CHUNK];

    const int tid = threadIdx.x;
    const int bb = blockIdx.x >> 8;           // / (L_DIM / GL_CHUNK) = / 256
    const int l0 = (blockIdx.x & 255) * GL_CHUNK;

    if (tid < GL_CHUNK) {
        int row = bb * L_DIM + l0 + tid;
        int code = combineRow(row);
        codes[tid] = code;
        if (out_code) out_code[row] = (float)code;
    }
    __syncthreads();

    // stage 8 rows: each warp loads one row via float4 (2KB coalesced)
    {
        const int w = tid >> 5, lane = tid & 31;
        const float4* src = (const float4*)(cb + (size_t)codes[w] * C_DIM);
        float4* dst = (float4*)&rows[w * GST];
        dst[lane]      = src[lane];
        dst[lane + 32] = src[lane + 32];
    }
    __syncthreads();

    const int c = tid;
    const size_t base = (size_t)bb * (C_DIM * L_DIM) + (size_t)c * L_DIM + l0;
    float4 e0, e1;
    e0.x = rows[0 * GST + c]; e0.y = rows[1 * GST + c];
    e0.z = rows[2 * GST + c]; e0.w = rows[3 * GST + c];
    e1.x = rows[4 * GST + c]; e1.y = rows[5 * GST + c];
    e1.z = rows[6 * GST + c]; e1.w = rows[7 * GST + c];
    float4 x0 = *(const float4*)&x[base];
    float4 x1 = *(const float4*)&x[base + 4];
    *(float4*)&emb_out[base]     = e0;
    *(float4*)&emb_out[base + 4] = e1;
    float d0 = x0.x - e0.x, d1 = x0.y - e0.y, d2 = x0.z - e0.z, d3 = x0.w - e0.w;
    float d4 = x1.x - e1.x, d5 = x1.y - e1.y, d6 = x1.z - e1.z, d7 = x1.w - e1.w;
    sred[tid] = d0 * d0 + d1 * d1 + d2 * d2 + d3 * d3
              + d4 * d4 + d5 * d5 + d6 * d6 + d7 * d7;
    __syncthreads();
    #pragma unroll
    for (int o = 128; o > 0; o >>= 1) {
        if (tid < o) sred[tid] += sred[tid + o];
        __syncthreads();
    }
    if (tid == 0) g_partial[blockIdx.x] = sred[0];
}

// ---------------- kernel 5: final loss reduction (1024 thr, shuffle) ---------
__global__ void finalize_kernel(float* __restrict__ loss_out) {
    __shared__ float warpsum[32];
    const int tid = threadIdx.x;
    const int lane = tid & 31, w = tid >> 5;
    float s = g_partial[tid] + g_partial[tid + 1024];
    #pragma unroll
    for (int o = 16; o > 0; o >>= 1) s += __shfl_xor_sync(0xffffffffu, s, o);
    if (lane == 0) warpsum[w] = s;
    __syncthreads();
    if (w == 0) {
        float t = warpsum[lane];
        #pragma unroll
        for (int o = 16; o > 0; o >>= 1) t += __shfl_xor_sync(0xffffffffu, t, o);
        if (lane == 0) loss_out[0] = t * (1.0f / (float)EMB_N);
    }
}

// ---------------- launch ------------------------------------------------------
extern "C" void kernel_launch(void* const* d_in, const int* in_sizes, int n_in,
                              void* d_out, int out_size) {
    const float* x  = (const float*)d_in[0];   // (8, 256, 2048)
    const float* cb = (const float*)d_in[1];   // (8192, 256)
    float* out = (float*)d_out;

    cudaFuncSetAttribute(argmax_kernel,
                         cudaFuncAttributeMaxDynamicSharedMemorySize, SMEM_BYTES);

    csq_kernel<<<K_CB / 8, 256>>>(cb);
    argmax_kernel<<<(M_DIM / BM) * NSPLIT, 256, SMEM_BYTES>>>(x, cb);

    const int full = M_DIM + EMB_N + 1;
    if (out_size >= full) {
        // layout: [code (16384), emb (4194304), loss (1)] in return order
        gather_loss_kernel<<<GL_BLOCKS, 256>>>(x, cb, out + M_DIM, out);
        finalize_kernel<<<1, 1024>>>(out + M_DIM + EMB_N);
    } else if (out_size == EMB_N) {
        gather_loss_kernel<<<GL_BLOCKS, 256>>>(x, cb, out, nullptr);
    } else if (out_size == M_DIM) {
        combine_cast_kernel<<<(M_DIM + 255) / 256, 256>>>(out);
    } else {
        gather_loss_kernel<<<GL_BLOCKS, 256>>>(x, cb, out, nullptr);
    }
}